// round 7
// baseline (speedup 1.0000x reference)
#include <cuda_runtime.h>
#include <cuda_fp16.h>
#include <cstdint>

#define D_MODEL 768
#define HEAD    64
#define BATCH   8
#define SEQ     2048
#define NROW    (BATCH * SEQ)

// Scale folded into Q: scores come out in log2 domain.
#define QSC 0.1803368801111244f   // 0.125 * log2(e)

// Scratch (no device allocation allowed).
__device__ __half g_Q[NROW * HEAD];
__device__ __half g_K[NROW * HEAD];
__device__ __half g_V[NROW * HEAD];
__device__ __half g_Wh[D_MODEL * 192];   // fp16 W, k-major [k][q|k|v] (Wq pre-scaled)

// ---------------------------------------------------------------------------
// common helpers
// ---------------------------------------------------------------------------
__device__ __forceinline__ uint32_t smem_u32(const void* p) {
    uint32_t a;
    asm("{ .reg .u64 t; cvta.to.shared.u64 t, %1; cvt.u32.u64 %0, t; }"
        : "=r"(a) : "l"(p));
    return a;
}
// 128B rows
__device__ __forceinline__ uint32_t sw_addr(uint32_t base, int row, int colh) {
    return base + row * 128 + (((uint32_t)(colh * 2)) ^ (((uint32_t)(row & 7)) << 4));
}
// 384B rows
__device__ __forceinline__ uint32_t sw_addr384(uint32_t base, int row, int colh) {
    return base + row * 384 + (((uint32_t)(colh * 2)) ^ (((uint32_t)(row & 7)) << 4));
}
__device__ __forceinline__ void ldsm_x4(uint32_t* r, uint32_t addr) {
    asm volatile("ldmatrix.sync.aligned.m8n8.x4.shared.b16 {%0,%1,%2,%3}, [%4];"
                 : "=r"(r[0]), "=r"(r[1]), "=r"(r[2]), "=r"(r[3]) : "r"(addr));
}
__device__ __forceinline__ void ldsm_x4_t(uint32_t* r, uint32_t addr) {
    asm volatile("ldmatrix.sync.aligned.m8n8.x4.trans.shared.b16 {%0,%1,%2,%3}, [%4];"
                 : "=r"(r[0]), "=r"(r[1]), "=r"(r[2]), "=r"(r[3]) : "r"(addr));
}
__device__ __forceinline__ void mma16816(float* d, const uint32_t* a, const uint32_t* b) {
    asm volatile(
        "mma.sync.aligned.m16n8k16.row.col.f32.f16.f16.f32 "
        "{%0,%1,%2,%3}, {%4,%5,%6,%7}, {%8,%9}, {%0,%1,%2,%3};"
        : "+f"(d[0]), "+f"(d[1]), "+f"(d[2]), "+f"(d[3])
        : "r"(a[0]), "r"(a[1]), "r"(a[2]), "r"(a[3]), "r"(b[0]), "r"(b[1]));
}
__device__ __forceinline__ float ex2f(float x) {
    float y;
    asm("ex2.approx.f32 %0, %1;" : "=f"(y) : "f"(x));
    return y;
}
#define CP16(dst, src) \
    asm volatile("cp.async.cg.shared.global [%0], [%1], 16;" \
                 :: "r"(dst), "l"(src) : "memory")
#define CP_COMMIT() asm volatile("cp.async.commit_group;" ::: "memory")

// ---------------------------------------------------------------------------
// Kernel 0: streaming fp32->fp16 convert of W (no transpose; k-major kept).
// g_Wh[k][0:64]=Wq[k]*QSC, [64:128]=Wk[k], [128:192]=Wv[k].
// grid 144 x 256: one float4 per thread.
// ---------------------------------------------------------------------------
__global__ __launch_bounds__(256) void wconv_kernel(
    const float* __restrict__ Wq, const float* __restrict__ Wk,
    const float* __restrict__ Wv)
{
    int idx = blockIdx.x * 256 + threadIdx.x;      // 0..36863 float4s
    int m   = idx / 12288;                          // matrix
    int rem = idx % 12288;
    int k   = rem >> 4, c4 = rem & 15;
    const float* Wm = (m == 0) ? Wq : (m == 1) ? Wk : Wv;
    float s = (m == 0) ? QSC : 1.0f;
    float4 v = *reinterpret_cast<const float4*>(&Wm[(size_t)k * 64 + c4 * 4]);
    __half2 h0 = __floats2half2_rn(v.x * s, v.y * s);
    __half2 h1 = __floats2half2_rn(v.z * s, v.w * s);
    uint2 hv = make_uint2(*reinterpret_cast<uint32_t*>(&h0),
                          *reinterpret_cast<uint32_t*>(&h1));
    *reinterpret_cast<uint2*>(&g_Wh[(size_t)k * 192 + m * 64 + c4 * 4]) = hv;
}

// ---------------------------------------------------------------------------
// Kernel 1: HMMA QKV projection. C[16384,192] = Xh · Wh (fp32 accumulate).
// BM=128, N=192, BK=64. W chunk k-major [64][192] in smem (384B rows),
// B fragments via ldmatrix.trans; W double-buffered via cp.async.
// ---------------------------------------------------------------------------
#define NCHUNK (D_MODEL / 64)
#define PXH 0
#define PWH0 16384
#define PWH1 40960
#define PROJ_SMEM 65536

__global__ __launch_bounds__(256, 1) void qkv_hmma_kernel(
    const float* __restrict__ x,
    const float* __restrict__ bq, const float* __restrict__ bk,
    const float* __restrict__ bv)
{
    extern __shared__ char sm[];
    const uint32_t sb = smem_u32(sm);
    const int tid  = threadIdx.x;
    const int lane = tid & 31;
    const int warp = tid >> 5;
    const int g    = lane >> 3, li = lane & 7;
    const int mw   = warp >> 1;
    const int nw   = warp & 1;
    const int row0 = blockIdx.x * 128;

    const uint32_t sWH[2] = { sb + PWH0, sb + PWH1 };

    // W chunk c: 64 k-rows x 384B = 1536 16B chunks.
    auto issue_w = [&](int c) {
#pragma unroll
        for (int i = 0; i < 6; i++) {
            int idx = tid + 256 * i;
            int k = idx / 24, c16 = idx % 24;
            uint32_t off = k * 384 + (((uint32_t)(c16 * 16)) ^ (((uint32_t)(k & 7)) << 4));
            CP16(sWH[c & 1] + off, g_Wh + (size_t)(c * 64 + k) * 192 + c16 * 8);
        }
    };

    float xr[32];
    auto ldg_x = [&](int c) {
#pragma unroll
        for (int i = 0; i < 8; i++) {
            int f = tid + 256 * i;
            int r = f >> 4, c4 = f & 15;
            float4 v = *reinterpret_cast<const float4*>(
                &x[(size_t)(row0 + r) * D_MODEL + c * 64 + c4 * 4]);
            xr[4 * i] = v.x; xr[4 * i + 1] = v.y; xr[4 * i + 2] = v.z; xr[4 * i + 3] = v.w;
        }
    };

    issue_w(0); CP_COMMIT();
    ldg_x(0);

    float acc[2][12][4];
#pragma unroll
    for (int mi = 0; mi < 2; mi++)
#pragma unroll
        for (int nj = 0; nj < 12; nj++)
#pragma unroll
            for (int i = 0; i < 4; i++) acc[mi][nj][i] = 0.f;

    for (int c = 0; c < NCHUNK; c++) {
        __syncthreads();
#pragma unroll
        for (int i = 0; i < 8; i++) {
            int f = tid + 256 * i;
            int r = f >> 4, c4 = f & 15;
            __half2 h0 = __floats2half2_rn(xr[4 * i],     xr[4 * i + 1]);
            __half2 h1 = __floats2half2_rn(xr[4 * i + 2], xr[4 * i + 3]);
            uint32_t off = r * 128 + (((uint32_t)(c4 * 8)) ^ (((uint32_t)(r & 7)) << 4));
            uint2 hv = make_uint2(*reinterpret_cast<uint32_t*>(&h0),
                                  *reinterpret_cast<uint32_t*>(&h1));
            *reinterpret_cast<uint2*>(sm + PXH + off) = hv;
        }
        if (c + 1 < NCHUNK) {
            issue_w(c + 1); CP_COMMIT();
            asm volatile("cp.async.wait_group 1;" ::: "memory");
        } else {
            asm volatile("cp.async.wait_group 0;" ::: "memory");
        }
        __syncthreads();
        if (c + 1 < NCHUNK) ldg_x(c + 1);

        const uint32_t whb = sWH[c & 1];
#pragma unroll
        for (int kk = 0; kk < 4; kk++) {
            uint32_t ah[2][4];
#pragma unroll
            for (int mi = 0; mi < 2; mi++) {
                int row  = mw * 32 + mi * 16 + (g & 1) * 8 + li;
                int colh = kk * 16 + (g >> 1) * 8;
                ldsm_x4(ah[mi], sw_addr(sb + PXH, row, colh));
            }
#pragma unroll
            for (int nj = 0; nj < 6; nj++) {
                uint32_t bh[4];
                int krow  = kk * 16 + (g & 1) * 8 + li;
                int ncolh = nw * 96 + nj * 16 + (g >> 1) * 8;
                ldsm_x4_t(bh, sw_addr384(whb, krow, ncolh));
#pragma unroll
                for (int mi = 0; mi < 2; mi++) {
                    mma16816(acc[mi][2 * nj],     ah[mi], &bh[0]);
                    mma16816(acc[mi][2 * nj + 1], ah[mi], &bh[2]);
                }
            }
        }
    }

    // epilogue: bias (Q bias scaled), fp16, scatter
    const int r  = lane >> 2;
    const int cc = (lane & 3) * 2;
    float2 biasv[12];
#pragma unroll
    for (int nj = 0; nj < 12; nj++) {
        int ncol = nw * 96 + nj * 8 + cc;
        const float* bp = (ncol < 64) ? bq : (ncol < 128) ? bk : bv;
        float s = (ncol < 64) ? QSC : 1.0f;
        int colw = ncol & 63;
        biasv[nj] = make_float2(bp[colw] * s, bp[colw + 1] * s);
    }
#pragma unroll
    for (int mi = 0; mi < 2; mi++) {
#pragma unroll
        for (int h = 0; h < 2; h++) {
            int grow = row0 + mw * 32 + mi * 16 + r + h * 8;
#pragma unroll
            for (int nj = 0; nj < 12; nj++) {
                int ncol = nw * 96 + nj * 8 + cc;
                __half* dst = (ncol < 64) ? g_Q : (ncol < 128) ? g_K : g_V;
                int colw = ncol & 63;
                __half2 v = __floats2half2_rn(acc[mi][nj][2 * h] + biasv[nj].x,
                                              acc[mi][nj][2 * h + 1] + biasv[nj].y);
                *reinterpret_cast<__half2*>(&dst[(size_t)grow * HEAD + colw]) = v;
            }
        }
    }
}

// ---------------------------------------------------------------------------
// Kernel 2: HMMA flash attention, fused slab loop.
// BM=64 (4 warps, 128 thr), BN=128; per 16-key slab: QK MMAs -> exp -> PV MMAs.
// Slabs are independent -> tensor/MUFU/LDSM overlap via scoreboarding.
// ---------------------------------------------------------------------------
#define BM 64
#define BN 128
#define NT (SEQ / BN)
#define OFF_Q   0
#define OFF_K0  8192
#define OFF_K1  24576
#define OFF_V0  40960
#define OFF_V1  57344
#define ATTN_SMEM 73728

__global__ __launch_bounds__(128) void attn_hmma_kernel(float* __restrict__ out)
{
    extern __shared__ char sm[];
    const uint32_t sb = smem_u32(sm);
    const int tid  = threadIdx.x;
    const int lane = tid & 31;
    const int warp = tid >> 5;
    const int b    = blockIdx.y;
    const int q0   = blockIdx.x * BM;
    const int qb   = warp * 16;

    const uint32_t sQ = sb + OFF_Q;
    const uint32_t sK[2] = { sb + OFF_K0, sb + OFF_K1 };
    const uint32_t sV[2] = { sb + OFF_V0, sb + OFF_V1 };

    auto issue_rows8 = [&](uint32_t dstbase, const __half* src, int row0g) {
#pragma unroll
        for (int i = 0; i < 8; i++) {
            int c   = tid + 128 * i;
            int row = c >> 3, c16 = c & 7;
            uint32_t dst = dstbase + row * 128 +
                (((uint32_t)(c16 * 16)) ^ (((uint32_t)(row & 7)) << 4));
            CP16(dst, src + (size_t)(row0g + row) * HEAD + c16 * 8);
        }
    };
    auto issue_rows4 = [&](uint32_t dstbase, const __half* src, int row0g) {
#pragma unroll
        for (int i = 0; i < 4; i++) {
            int c   = tid + 128 * i;
            int row = c >> 3, c16 = c & 7;
            uint32_t dst = dstbase + row * 128 +
                (((uint32_t)(c16 * 16)) ^ (((uint32_t)(row & 7)) << 4));
            CP16(dst, src + (size_t)(row0g + row) * HEAD + c16 * 8);
        }
    };

    issue_rows4(sQ, g_Q, b * SEQ + q0);
    issue_rows8(sK[0], g_K, b * SEQ);
    issue_rows8(sV[0], g_V, b * SEQ);
    CP_COMMIT();

    const int g = lane >> 3, li = lane & 7;

    uint32_t qf[4][4];
    float    O[8][4];
#pragma unroll
    for (int n = 0; n < 8; n++)
#pragma unroll
        for (int i = 0; i < 4; i++) O[n][i] = 0.f;
    float lsum0 = 0.f, lsum1 = 0.f;

    for (int t = 0; t < NT; t++) {
        if (t + 1 < NT) {
            issue_rows8(sK[(t + 1) & 1], g_K, b * SEQ + (t + 1) * BN);
            issue_rows8(sV[(t + 1) & 1], g_V, b * SEQ + (t + 1) * BN);
            CP_COMMIT();
            asm volatile("cp.async.wait_group 1;" ::: "memory");
        } else {
            asm volatile("cp.async.wait_group 0;" ::: "memory");
        }
        __syncthreads();

        if (t == 0) {
#pragma unroll
            for (int kk = 0; kk < 4; kk++) {
                int row  = qb + (g & 1) * 8 + li;
                int colh = kk * 16 + (g >> 1) * 8;
                ldsm_x4(qf[kk], sw_addr(sQ, row, colh));
            }
        }

        const uint32_t kbuf = sK[t & 1], vbuf = sV[t & 1];

        // fused slab loop: 16 keys per iteration
#pragma unroll
        for (int j = 0; j < 8; j++) {
            float s0[4] = {0.f, 0.f, 0.f, 0.f};
            float s1[4] = {0.f, 0.f, 0.f, 0.f};
#pragma unroll
            for (int kk = 0; kk < 4; kk++) {
                uint32_t kb[4];
                int row  = j * 16 + (g >> 1) * 8 + li;
                int colh = kk * 16 + (g & 1) * 8;
                ldsm_x4(kb, sw_addr(kbuf, row, colh));
                mma16816(s0, qf[kk], &kb[0]);
                mma16816(s1, qf[kk], &kb[2]);
            }

            float e00 = ex2f(s0[0]);
            float e01 = ex2f(s0[1]);
            float e02 = ex2f(s0[2]);
            float e03 = ex2f(s0[3]);
            float e10 = ex2f(s1[0]);
            float e11 = ex2f(s1[1]);
            float e12 = ex2f(s1[2]);
            float e13 = ex2f(s1[3]);
            lsum0 += (e00 + e01) + (e10 + e11);
            lsum1 += (e02 + e03) + (e12 + e13);

            uint32_t pa[4];
            __half2 h;
            h = __floats2half2_rn(e00, e01); pa[0] = *reinterpret_cast<uint32_t*>(&h);
            h = __floats2half2_rn(e02, e03); pa[1] = *reinterpret_cast<uint32_t*>(&h);
            h = __floats2half2_rn(e10, e11); pa[2] = *reinterpret_cast<uint32_t*>(&h);
            h = __floats2half2_rn(e12, e13); pa[3] = *reinterpret_cast<uint32_t*>(&h);

#pragma unroll
            for (int p = 0; p < 4; p++) {
                uint32_t vb[4];
                int row  = j * 16 + (g & 1) * 8 + li;
                int colh = p * 16 + (g >> 1) * 8;
                ldsm_x4_t(vb, sw_addr(vbuf, row, colh));
                mma16816(O[2 * p],     pa, &vb[0]);
                mma16816(O[2 * p + 1], pa, &vb[2]);
            }
        }
        __syncthreads();
    }

    lsum0 += __shfl_xor_sync(0xffffffffu, lsum0, 1);
    lsum0 += __shfl_xor_sync(0xffffffffu, lsum0, 2);
    lsum1 += __shfl_xor_sync(0xffffffffu, lsum1, 1);
    lsum1 += __shfl_xor_sync(0xffffffffu, lsum1, 2);
    const float inv0 = 1.f / lsum0;
    const float inv1 = 1.f / lsum1;

    const int r  = lane >> 2;
    const int cc = (lane & 3) * 2;
    float* row0p = &out[(size_t)(b * SEQ + q0 + qb + r) * HEAD];
    float* row1p = &out[(size_t)(b * SEQ + q0 + qb + r + 8) * HEAD];
#pragma unroll
    for (int nb = 0; nb < 8; nb++) {
        float2 v0 = make_float2(O[nb][0] * inv0, O[nb][1] * inv0);
        float2 v1 = make_float2(O[nb][2] * inv1, O[nb][3] * inv1);
        *reinterpret_cast<float2*>(row0p + nb * 8 + cc) = v0;
        *reinterpret_cast<float2*>(row1p + nb * 8 + cc) = v1;
    }
}

// ---------------------------------------------------------------------------
extern "C" void kernel_launch(void* const* d_in, const int* in_sizes, int n_in,
                              void* d_out, int out_size)
{
    const float* x  = (const float*)d_in[0];
    const float* Wq = (const float*)d_in[1];
    const float* bq = (const float*)d_in[2];
    const float* Wk = (const float*)d_in[3];
    const float* bk = (const float*)d_in[4];
    const float* Wv = (const float*)d_in[5];
    const float* bv = (const float*)d_in[6];
    float* out = (float*)d_out;

    wconv_kernel<<<144, 256>>>(Wq, Wk, Wv);

    cudaFuncSetAttribute(qkv_hmma_kernel,
                         cudaFuncAttributeMaxDynamicSharedMemorySize, PROJ_SMEM);
    qkv_hmma_kernel<<<NROW / 128, 256, PROJ_SMEM>>>(x, bq, bk, bv);

    cudaFuncSetAttribute(attn_hmma_kernel,
                         cudaFuncAttributeMaxDynamicSharedMemorySize, ATTN_SMEM);
    attn_hmma_kernel<<<dim3(SEQ / BM, BATCH), 128, ATTN_SMEM>>>(out);
}

// round 8
// speedup vs baseline: 1.0036x; 1.0036x over previous
#include <cuda_runtime.h>
#include <cuda_fp16.h>
#include <cstdint>

#define D_MODEL 768
#define HEAD    64
#define BATCH   8
#define SEQ     2048
#define NROW    (BATCH * SEQ)

// Scale folded into Q: scores come out in log2 domain.
#define QSC 0.1803368801111244f   // 0.125 * log2(e)

// Scratch (no device allocation allowed).
__device__ __half g_Q[NROW * HEAD];
__device__ __half g_K[NROW * HEAD];
__device__ __half g_V[NROW * HEAD];
__device__ __half g_Wh[D_MODEL * 192];   // fp16 W, k-major [k][q|k|v] (Wq pre-scaled)

// ---------------------------------------------------------------------------
// common helpers
// ---------------------------------------------------------------------------
__device__ __forceinline__ uint32_t smem_u32(const void* p) {
    uint32_t a;
    asm("{ .reg .u64 t; cvta.to.shared.u64 t, %1; cvt.u32.u64 %0, t; }"
        : "=r"(a) : "l"(p));
    return a;
}
// 128B rows
__device__ __forceinline__ uint32_t sw_addr(uint32_t base, int row, int colh) {
    return base + row * 128 + (((uint32_t)(colh * 2)) ^ (((uint32_t)(row & 7)) << 4));
}
// 384B rows
__device__ __forceinline__ uint32_t sw_addr384(uint32_t base, int row, int colh) {
    return base + row * 384 + (((uint32_t)(colh * 2)) ^ (((uint32_t)(row & 7)) << 4));
}
__device__ __forceinline__ void ldsm_x4(uint32_t* r, uint32_t addr) {
    asm volatile("ldmatrix.sync.aligned.m8n8.x4.shared.b16 {%0,%1,%2,%3}, [%4];"
                 : "=r"(r[0]), "=r"(r[1]), "=r"(r[2]), "=r"(r[3]) : "r"(addr));
}
__device__ __forceinline__ void ldsm_x4_t(uint32_t* r, uint32_t addr) {
    asm volatile("ldmatrix.sync.aligned.m8n8.x4.trans.shared.b16 {%0,%1,%2,%3}, [%4];"
                 : "=r"(r[0]), "=r"(r[1]), "=r"(r[2]), "=r"(r[3]) : "r"(addr));
}
__device__ __forceinline__ void mma16816(float* d, const uint32_t* a, const uint32_t* b) {
    asm volatile(
        "mma.sync.aligned.m16n8k16.row.col.f32.f16.f16.f32 "
        "{%0,%1,%2,%3}, {%4,%5,%6,%7}, {%8,%9}, {%0,%1,%2,%3};"
        : "+f"(d[0]), "+f"(d[1]), "+f"(d[2]), "+f"(d[3])
        : "r"(a[0]), "r"(a[1]), "r"(a[2]), "r"(a[3]), "r"(b[0]), "r"(b[1]));
}
__device__ __forceinline__ float ex2f(float x) {
    float y;
    asm("ex2.approx.f32 %0, %1;" : "=f"(y) : "f"(x));
    return y;
}
#define CP16(dst, src) \
    asm volatile("cp.async.cg.shared.global [%0], [%1], 16;" \
                 :: "r"(dst), "l"(src) : "memory")
#define CP_COMMIT() asm volatile("cp.async.commit_group;" ::: "memory")

// ---------------------------------------------------------------------------
// Kernel 0: streaming fp32->fp16 convert of W (no transpose; k-major kept).
// g_Wh[k][0:64]=Wq[k]*QSC, [64:128]=Wk[k], [128:192]=Wv[k].
// grid 144 x 256: one float4 per thread.
// ---------------------------------------------------------------------------
__global__ __launch_bounds__(256) void wconv_kernel(
    const float* __restrict__ Wq, const float* __restrict__ Wk,
    const float* __restrict__ Wv)
{
    int idx = blockIdx.x * 256 + threadIdx.x;      // 0..36863 float4s
    int m   = idx / 12288;                          // matrix
    int rem = idx % 12288;
    int k   = rem >> 4, c4 = rem & 15;
    const float* Wm = (m == 0) ? Wq : (m == 1) ? Wk : Wv;
    float s = (m == 0) ? QSC : 1.0f;
    float4 v = *reinterpret_cast<const float4*>(&Wm[(size_t)k * 64 + c4 * 4]);
    __half2 h0 = __floats2half2_rn(v.x * s, v.y * s);
    __half2 h1 = __floats2half2_rn(v.z * s, v.w * s);
    uint2 hv = make_uint2(*reinterpret_cast<uint32_t*>(&h0),
                          *reinterpret_cast<uint32_t*>(&h1));
    *reinterpret_cast<uint2*>(&g_Wh[(size_t)k * 192 + m * 64 + c4 * 4]) = hv;
}

// ---------------------------------------------------------------------------
// Kernel 1: HMMA QKV projection. C[16384,192] = Xh · Wh (fp32 accumulate).
// BM=128, N=192, BK=64. W chunk k-major [64][192] in smem (384B rows),
// B fragments via ldmatrix.trans; W double-buffered via cp.async.
// ---------------------------------------------------------------------------
#define NCHUNK (D_MODEL / 64)
#define PXH 0
#define PWH0 16384
#define PWH1 40960
#define PROJ_SMEM 65536

__global__ __launch_bounds__(256, 1) void qkv_hmma_kernel(
    const float* __restrict__ x,
    const float* __restrict__ bq, const float* __restrict__ bk,
    const float* __restrict__ bv)
{
    extern __shared__ char sm[];
    const uint32_t sb = smem_u32(sm);
    const int tid  = threadIdx.x;
    const int lane = tid & 31;
    const int warp = tid >> 5;
    const int g    = lane >> 3, li = lane & 7;
    const int mw   = warp >> 1;
    const int nw   = warp & 1;
    const int row0 = blockIdx.x * 128;

    const uint32_t sWH[2] = { sb + PWH0, sb + PWH1 };

    // W chunk c: 64 k-rows x 384B = 1536 16B chunks.
    auto issue_w = [&](int c) {
#pragma unroll
        for (int i = 0; i < 6; i++) {
            int idx = tid + 256 * i;
            int k = idx / 24, c16 = idx % 24;
            uint32_t off = k * 384 + (((uint32_t)(c16 * 16)) ^ (((uint32_t)(k & 7)) << 4));
            CP16(sWH[c & 1] + off, g_Wh + (size_t)(c * 64 + k) * 192 + c16 * 8);
        }
    };

    float xr[32];
    auto ldg_x = [&](int c) {
#pragma unroll
        for (int i = 0; i < 8; i++) {
            int f = tid + 256 * i;
            int r = f >> 4, c4 = f & 15;
            float4 v = *reinterpret_cast<const float4*>(
                &x[(size_t)(row0 + r) * D_MODEL + c * 64 + c4 * 4]);
            xr[4 * i] = v.x; xr[4 * i + 1] = v.y; xr[4 * i + 2] = v.z; xr[4 * i + 3] = v.w;
        }
    };

    issue_w(0); CP_COMMIT();
    ldg_x(0);

    float acc[2][12][4];
#pragma unroll
    for (int mi = 0; mi < 2; mi++)
#pragma unroll
        for (int nj = 0; nj < 12; nj++)
#pragma unroll
            for (int i = 0; i < 4; i++) acc[mi][nj][i] = 0.f;

    for (int c = 0; c < NCHUNK; c++) {
        __syncthreads();
#pragma unroll
        for (int i = 0; i < 8; i++) {
            int f = tid + 256 * i;
            int r = f >> 4, c4 = f & 15;
            __half2 h0 = __floats2half2_rn(xr[4 * i],     xr[4 * i + 1]);
            __half2 h1 = __floats2half2_rn(xr[4 * i + 2], xr[4 * i + 3]);
            uint32_t off = r * 128 + (((uint32_t)(c4 * 8)) ^ (((uint32_t)(r & 7)) << 4));
            uint2 hv = make_uint2(*reinterpret_cast<uint32_t*>(&h0),
                                  *reinterpret_cast<uint32_t*>(&h1));
            *reinterpret_cast<uint2*>(sm + PXH + off) = hv;
        }
        if (c + 1 < NCHUNK) {
            issue_w(c + 1); CP_COMMIT();
            asm volatile("cp.async.wait_group 1;" ::: "memory");
        } else {
            asm volatile("cp.async.wait_group 0;" ::: "memory");
        }
        __syncthreads();
        if (c + 1 < NCHUNK) ldg_x(c + 1);

        const uint32_t whb = sWH[c & 1];
#pragma unroll
        for (int kk = 0; kk < 4; kk++) {
            uint32_t ah[2][4];
#pragma unroll
            for (int mi = 0; mi < 2; mi++) {
                int row  = mw * 32 + mi * 16 + (g & 1) * 8 + li;
                int colh = kk * 16 + (g >> 1) * 8;
                ldsm_x4(ah[mi], sw_addr(sb + PXH, row, colh));
            }
#pragma unroll
            for (int nj = 0; nj < 6; nj++) {
                uint32_t bh[4];
                int krow  = kk * 16 + (g & 1) * 8 + li;
                int ncolh = nw * 96 + nj * 16 + (g >> 1) * 8;
                ldsm_x4_t(bh, sw_addr384(whb, krow, ncolh));
#pragma unroll
                for (int mi = 0; mi < 2; mi++) {
                    mma16816(acc[mi][2 * nj],     ah[mi], &bh[0]);
                    mma16816(acc[mi][2 * nj + 1], ah[mi], &bh[2]);
                }
            }
        }
    }

    // epilogue: bias (Q bias scaled), fp16, scatter
    const int r  = lane >> 2;
    const int cc = (lane & 3) * 2;
    float2 biasv[12];
#pragma unroll
    for (int nj = 0; nj < 12; nj++) {
        int ncol = nw * 96 + nj * 8 + cc;
        const float* bp = (ncol < 64) ? bq : (ncol < 128) ? bk : bv;
        float s = (ncol < 64) ? QSC : 1.0f;
        int colw = ncol & 63;
        biasv[nj] = make_float2(bp[colw] * s, bp[colw + 1] * s);
    }
#pragma unroll
    for (int mi = 0; mi < 2; mi++) {
#pragma unroll
        for (int h = 0; h < 2; h++) {
            int grow = row0 + mw * 32 + mi * 16 + r + h * 8;
#pragma unroll
            for (int nj = 0; nj < 12; nj++) {
                int ncol = nw * 96 + nj * 8 + cc;
                __half* dst = (ncol < 64) ? g_Q : (ncol < 128) ? g_K : g_V;
                int colw = ncol & 63;
                __half2 v = __floats2half2_rn(acc[mi][nj][2 * h] + biasv[nj].x,
                                              acc[mi][nj][2 * h + 1] + biasv[nj].y);
                *reinterpret_cast<__half2*>(&dst[(size_t)grow * HEAD + colw]) = v;
            }
        }
    }
}

// ---------------------------------------------------------------------------
// Kernel 2: HMMA flash attention, fused slab loop.
// BM=64 (4 warps, 128 thr), BN=128; per 16-key slab: QK MMAs -> exp -> PV MMAs.
// Slabs are independent -> tensor/MUFU/LDSM overlap via scoreboarding.
// ---------------------------------------------------------------------------
#define BM 64
#define BN 128
#define NT (SEQ / BN)
#define OFF_Q   0
#define OFF_K0  8192
#define OFF_K1  24576
#define OFF_V0  40960
#define OFF_V1  57344
#define ATTN_SMEM 73728

__global__ __launch_bounds__(128) void attn_hmma_kernel(float* __restrict__ out)
{
    extern __shared__ char sm[];
    const uint32_t sb = smem_u32(sm);
    const int tid  = threadIdx.x;
    const int lane = tid & 31;
    const int warp = tid >> 5;
    const int b    = blockIdx.y;
    const int q0   = blockIdx.x * BM;
    const int qb   = warp * 16;

    const uint32_t sQ = sb + OFF_Q;
    const uint32_t sK[2] = { sb + OFF_K0, sb + OFF_K1 };
    const uint32_t sV[2] = { sb + OFF_V0, sb + OFF_V1 };

    auto issue_rows8 = [&](uint32_t dstbase, const __half* src, int row0g) {
#pragma unroll
        for (int i = 0; i < 8; i++) {
            int c   = tid + 128 * i;
            int row = c >> 3, c16 = c & 7;
            uint32_t dst = dstbase + row * 128 +
                (((uint32_t)(c16 * 16)) ^ (((uint32_t)(row & 7)) << 4));
            CP16(dst, src + (size_t)(row0g + row) * HEAD + c16 * 8);
        }
    };
    auto issue_rows4 = [&](uint32_t dstbase, const __half* src, int row0g) {
#pragma unroll
        for (int i = 0; i < 4; i++) {
            int c   = tid + 128 * i;
            int row = c >> 3, c16 = c & 7;
            uint32_t dst = dstbase + row * 128 +
                (((uint32_t)(c16 * 16)) ^ (((uint32_t)(row & 7)) << 4));
            CP16(dst, src + (size_t)(row0g + row) * HEAD + c16 * 8);
        }
    };

    issue_rows4(sQ, g_Q, b * SEQ + q0);
    issue_rows8(sK[0], g_K, b * SEQ);
    issue_rows8(sV[0], g_V, b * SEQ);
    CP_COMMIT();

    const int g = lane >> 3, li = lane & 7;

    uint32_t qf[4][4];
    float    O[8][4];
#pragma unroll
    for (int n = 0; n < 8; n++)
#pragma unroll
        for (int i = 0; i < 4; i++) O[n][i] = 0.f;
    float lsum0 = 0.f, lsum1 = 0.f;

    for (int t = 0; t < NT; t++) {
        if (t + 1 < NT) {
            issue_rows8(sK[(t + 1) & 1], g_K, b * SEQ + (t + 1) * BN);
            issue_rows8(sV[(t + 1) & 1], g_V, b * SEQ + (t + 1) * BN);
            CP_COMMIT();
            asm volatile("cp.async.wait_group 1;" ::: "memory");
        } else {
            asm volatile("cp.async.wait_group 0;" ::: "memory");
        }
        __syncthreads();

        if (t == 0) {
#pragma unroll
            for (int kk = 0; kk < 4; kk++) {
                int row  = qb + (g & 1) * 8 + li;
                int colh = kk * 16 + (g >> 1) * 8;
                ldsm_x4(qf[kk], sw_addr(sQ, row, colh));
            }
        }

        const uint32_t kbuf = sK[t & 1], vbuf = sV[t & 1];

        // fused slab loop: 16 keys per iteration
#pragma unroll
        for (int j = 0; j < 8; j++) {
            float s0[4] = {0.f, 0.f, 0.f, 0.f};
            float s1[4] = {0.f, 0.f, 0.f, 0.f};
#pragma unroll
            for (int kk = 0; kk < 4; kk++) {
                uint32_t kb[4];
                int row  = j * 16 + (g >> 1) * 8 + li;
                int colh = kk * 16 + (g & 1) * 8;
                ldsm_x4(kb, sw_addr(kbuf, row, colh));
                mma16816(s0, qf[kk], &kb[0]);
                mma16816(s1, qf[kk], &kb[2]);
            }

            float e00 = ex2f(s0[0]);
            float e01 = ex2f(s0[1]);
            float e02 = ex2f(s0[2]);
            float e03 = ex2f(s0[3]);
            float e10 = ex2f(s1[0]);
            float e11 = ex2f(s1[1]);
            float e12 = ex2f(s1[2]);
            float e13 = ex2f(s1[3]);
            lsum0 += (e00 + e01) + (e10 + e11);
            lsum1 += (e02 + e03) + (e12 + e13);

            uint32_t pa[4];
            __half2 h;
            h = __floats2half2_rn(e00, e01); pa[0] = *reinterpret_cast<uint32_t*>(&h);
            h = __floats2half2_rn(e02, e03); pa[1] = *reinterpret_cast<uint32_t*>(&h);
            h = __floats2half2_rn(e10, e11); pa[2] = *reinterpret_cast<uint32_t*>(&h);
            h = __floats2half2_rn(e12, e13); pa[3] = *reinterpret_cast<uint32_t*>(&h);

#pragma unroll
            for (int p = 0; p < 4; p++) {
                uint32_t vb[4];
                int row  = j * 16 + (g & 1) * 8 + li;
                int colh = p * 16 + (g >> 1) * 8;
                ldsm_x4_t(vb, sw_addr(vbuf, row, colh));
                mma16816(O[2 * p],     pa, &vb[0]);
                mma16816(O[2 * p + 1], pa, &vb[2]);
            }
        }
        __syncthreads();
    }

    lsum0 += __shfl_xor_sync(0xffffffffu, lsum0, 1);
    lsum0 += __shfl_xor_sync(0xffffffffu, lsum0, 2);
    lsum1 += __shfl_xor_sync(0xffffffffu, lsum1, 1);
    lsum1 += __shfl_xor_sync(0xffffffffu, lsum1, 2);
    const float inv0 = 1.f / lsum0;
    const float inv1 = 1.f / lsum1;

    const int r  = lane >> 2;
    const int cc = (lane & 3) * 2;
    float* row0p = &out[(size_t)(b * SEQ + q0 + qb + r) * HEAD];
    float* row1p = &out[(size_t)(b * SEQ + q0 + qb + r + 8) * HEAD];
#pragma unroll
    for (int nb = 0; nb < 8; nb++) {
        float2 v0 = make_float2(O[nb][0] * inv0, O[nb][1] * inv0);
        float2 v1 = make_float2(O[nb][2] * inv1, O[nb][3] * inv1);
        *reinterpret_cast<float2*>(row0p + nb * 8 + cc) = v0;
        *reinterpret_cast<float2*>(row1p + nb * 8 + cc) = v1;
    }
}

// ---------------------------------------------------------------------------
extern "C" void kernel_launch(void* const* d_in, const int* in_sizes, int n_in,
                              void* d_out, int out_size)
{
    const float* x  = (const float*)d_in[0];
    const float* Wq = (const float*)d_in[1];
    const float* bq = (const float*)d_in[2];
    const float* Wk = (const float*)d_in[3];
    const float* bk = (const float*)d_in[4];
    const float* Wv = (const float*)d_in[5];
    const float* bv = (const float*)d_in[6];
    float* out = (float*)d_out;

    wconv_kernel<<<144, 256>>>(Wq, Wk, Wv);

    cudaFuncSetAttribute(qkv_hmma_kernel,
                         cudaFuncAttributeMaxDynamicSharedMemorySize, PROJ_SMEM);
    qkv_hmma_kernel<<<NROW / 128, 256, PROJ_SMEM>>>(x, bq, bk, bv);

    cudaFuncSetAttribute(attn_hmma_kernel,
                         cudaFuncAttributeMaxDynamicSharedMemorySize, ATTN_SMEM);
    attn_hmma_kernel<<<dim3(SEQ / BM, BATCH), 128, ATTN_SMEM>>>(out);
}

// round 9
// speedup vs baseline: 1.0052x; 1.0016x over previous
#include <cuda_runtime.h>
#include <cuda_fp16.h>
#include <cstdint>

#define D_MODEL 768
#define HEAD    64
#define BATCH   8
#define SEQ     2048
#define NROW    (BATCH * SEQ)
#define NSPLIT  2
#define KSPLIT  (SEQ / NSPLIT)

// Scale folded into Q: scores come out in log2 domain.
#define QSC 0.1803368801111244f   // 0.125 * log2(e)

// Scratch (no device allocation allowed).
__device__ __half g_Q[NROW * HEAD];
__device__ __half g_K[NROW * HEAD];
__device__ __half g_V[NROW * HEAD];
__device__ __half g_Wth[192 * D_MODEL];          // W^T fp16 [n][k] (Wq pre-scaled)
__device__ float  g_Opart[NSPLIT * NROW * HEAD]; // unnormalized partial O
__device__ float  g_Lpart[NSPLIT * NROW];        // partial exp-sums

// ---------------------------------------------------------------------------
// common helpers
// ---------------------------------------------------------------------------
__device__ __forceinline__ uint32_t smem_u32(const void* p) {
    uint32_t a;
    asm("{ .reg .u64 t; cvta.to.shared.u64 t, %1; cvt.u32.u64 %0, t; }"
        : "=r"(a) : "l"(p));
    return a;
}
// 128B rows
__device__ __forceinline__ uint32_t sw_addr(uint32_t base, int row, int colh) {
    return base + row * 128 + (((uint32_t)(colh * 2)) ^ (((uint32_t)(row & 7)) << 4));
}
__device__ __forceinline__ void ldsm_x4(uint32_t* r, uint32_t addr) {
    asm volatile("ldmatrix.sync.aligned.m8n8.x4.shared.b16 {%0,%1,%2,%3}, [%4];"
                 : "=r"(r[0]), "=r"(r[1]), "=r"(r[2]), "=r"(r[3]) : "r"(addr));
}
__device__ __forceinline__ void ldsm_x4_t(uint32_t* r, uint32_t addr) {
    asm volatile("ldmatrix.sync.aligned.m8n8.x4.trans.shared.b16 {%0,%1,%2,%3}, [%4];"
                 : "=r"(r[0]), "=r"(r[1]), "=r"(r[2]), "=r"(r[3]) : "r"(addr));
}
__device__ __forceinline__ void mma16816(float* d, const uint32_t* a, const uint32_t* b) {
    asm volatile(
        "mma.sync.aligned.m16n8k16.row.col.f32.f16.f16.f32 "
        "{%0,%1,%2,%3}, {%4,%5,%6,%7}, {%8,%9}, {%0,%1,%2,%3};"
        : "+f"(d[0]), "+f"(d[1]), "+f"(d[2]), "+f"(d[3])
        : "r"(a[0]), "r"(a[1]), "r"(a[2]), "r"(a[3]), "r"(b[0]), "r"(b[1]));
}
__device__ __forceinline__ float ex2f(float x) {
    float y;
    asm("ex2.approx.f32 %0, %1;" : "=f"(y) : "f"(x));
    return y;
}
#define CP16(dst, src) \
    asm volatile("cp.async.cg.shared.global [%0], [%1], 16;" \
                 :: "r"(dst), "l"(src) : "memory")
#define CP_COMMIT() asm volatile("cp.async.commit_group;" ::: "memory")

// ---------------------------------------------------------------------------
// Kernel 0: W transpose + fp16 convert -> g_Wth [n][k] (Wq scaled by QSC).
// grid (24, 3): 32-k x 64-n tiles, 256 threads, vectorized.
// ---------------------------------------------------------------------------
__global__ __launch_bounds__(256) void wsplit_kernel(
    const float* __restrict__ Wq, const float* __restrict__ Wk,
    const float* __restrict__ Wv)
{
    __shared__ float tile[32][65];
    const float* W = (blockIdx.y == 0) ? Wq : (blockIdx.y == 1) ? Wk : Wv;
    const float sc = (blockIdx.y == 0) ? QSC : 1.0f;
    const int kbase = blockIdx.x * 32;
    const int tid = threadIdx.x;
    // load: 512 float4 (32 k-rows x 16 f4), 2 per thread
#pragma unroll
    for (int i = 0; i < 2; i++) {
        int f4 = tid + 256 * i;
        int k = f4 >> 4, c4 = f4 & 15;
        float4 v = *reinterpret_cast<const float4*>(&W[(size_t)(kbase + k) * 64 + c4 * 4]);
        tile[k][c4 * 4 + 0] = v.x;
        tile[k][c4 * 4 + 1] = v.y;
        tile[k][c4 * 4 + 2] = v.z;
        tile[k][c4 * 4 + 3] = v.w;
    }
    __syncthreads();
    // store: 1024 half2 (64 n x 16 k-pairs), 4 per thread, coalesced along k
#pragma unroll
    for (int j = 0; j < 4; j++) {
        int idx = tid + 256 * j;
        int n = idx >> 4, kp = idx & 15;
        __half2 h = __floats2half2_rn(tile[2 * kp][n] * sc, tile[2 * kp + 1][n] * sc);
        *reinterpret_cast<__half2*>(
            &g_Wth[(size_t)(blockIdx.y * 64 + n) * D_MODEL + kbase + 2 * kp]) = h;
    }
}

// ---------------------------------------------------------------------------
// Kernel 1: HMMA QKV projection (round-5 proven structure).
// C[16384,192] = Xh · Wh (fp32 accumulate). BM=128, N=192, BK=64.
// ---------------------------------------------------------------------------
#define NCHUNK (D_MODEL / 64)
#define PXH 0
#define PWH0 16384
#define PWH1 40960
#define PROJ_SMEM 65536

__global__ __launch_bounds__(256, 1) void qkv_hmma_kernel(
    const float* __restrict__ x,
    const float* __restrict__ bq, const float* __restrict__ bk,
    const float* __restrict__ bv)
{
    extern __shared__ char sm[];
    const uint32_t sb = smem_u32(sm);
    const int tid  = threadIdx.x;
    const int lane = tid & 31;
    const int warp = tid >> 5;
    const int g    = lane >> 3, li = lane & 7;
    const int mw   = warp >> 1;
    const int nw   = warp & 1;
    const int row0 = blockIdx.x * 128;

    const uint32_t sWH[2] = { sb + PWH0, sb + PWH1 };

    auto issue_w = [&](int c) {
#pragma unroll
        for (int i = 0; i < 6; i++) {
            int idx = tid + 256 * i;
            int n = idx >> 3, c16 = idx & 7;
            uint32_t off = n * 128 + (((uint32_t)(c16 * 16)) ^ (((uint32_t)(n & 7)) << 4));
            CP16(sWH[c & 1] + off, g_Wth + (size_t)n * D_MODEL + c * 64 + c16 * 8);
        }
    };

    float xr[32];
    auto ldg_x = [&](int c) {
#pragma unroll
        for (int i = 0; i < 8; i++) {
            int f = tid + 256 * i;
            int r = f >> 4, c4 = f & 15;
            float4 v = *reinterpret_cast<const float4*>(
                &x[(size_t)(row0 + r) * D_MODEL + c * 64 + c4 * 4]);
            xr[4 * i] = v.x; xr[4 * i + 1] = v.y; xr[4 * i + 2] = v.z; xr[4 * i + 3] = v.w;
        }
    };

    issue_w(0); CP_COMMIT();
    ldg_x(0);

    float acc[2][12][4];
#pragma unroll
    for (int mi = 0; mi < 2; mi++)
#pragma unroll
        for (int nj = 0; nj < 12; nj++)
#pragma unroll
            for (int i = 0; i < 4; i++) acc[mi][nj][i] = 0.f;

    for (int c = 0; c < NCHUNK; c++) {
        __syncthreads();
#pragma unroll
        for (int i = 0; i < 8; i++) {
            int f = tid + 256 * i;
            int r = f >> 4, c4 = f & 15;
            __half2 h0 = __floats2half2_rn(xr[4 * i],     xr[4 * i + 1]);
            __half2 h1 = __floats2half2_rn(xr[4 * i + 2], xr[4 * i + 3]);
            uint32_t off = r * 128 + (((uint32_t)(c4 * 8)) ^ (((uint32_t)(r & 7)) << 4));
            uint2 hv = make_uint2(*reinterpret_cast<uint32_t*>(&h0),
                                  *reinterpret_cast<uint32_t*>(&h1));
            *reinterpret_cast<uint2*>(sm + PXH + off) = hv;
        }
        if (c + 1 < NCHUNK) {
            issue_w(c + 1); CP_COMMIT();
            asm volatile("cp.async.wait_group 1;" ::: "memory");
        } else {
            asm volatile("cp.async.wait_group 0;" ::: "memory");
        }
        __syncthreads();
        if (c + 1 < NCHUNK) ldg_x(c + 1);

        const uint32_t whb = sWH[c & 1];
#pragma unroll
        for (int kk = 0; kk < 4; kk++) {
            uint32_t ah[2][4];
#pragma unroll
            for (int mi = 0; mi < 2; mi++) {
                int row  = mw * 32 + mi * 16 + (g & 1) * 8 + li;
                int colh = kk * 16 + (g >> 1) * 8;
                ldsm_x4(ah[mi], sw_addr(sb + PXH, row, colh));
            }
#pragma unroll
            for (int nj = 0; nj < 6; nj++) {
                uint32_t bh[4];
                int nrow = nw * 96 + nj * 16 + (g >> 1) * 8 + li;
                int colh = kk * 16 + (g & 1) * 8;
                ldsm_x4(bh, sw_addr(whb, nrow, colh));
#pragma unroll
                for (int mi = 0; mi < 2; mi++) {
                    mma16816(acc[mi][2 * nj],     ah[mi], &bh[0]);
                    mma16816(acc[mi][2 * nj + 1], ah[mi], &bh[2]);
                }
            }
        }
    }

    const int r  = lane >> 2;
    const int cc = (lane & 3) * 2;
    float2 biasv[12];
#pragma unroll
    for (int nj = 0; nj < 12; nj++) {
        int ncol = nw * 96 + nj * 8 + cc;
        const float* bp = (ncol < 64) ? bq : (ncol < 128) ? bk : bv;
        float s = (ncol < 64) ? QSC : 1.0f;
        int colw = ncol & 63;
        biasv[nj] = make_float2(bp[colw] * s, bp[colw + 1] * s);
    }
#pragma unroll
    for (int mi = 0; mi < 2; mi++) {
#pragma unroll
        for (int h = 0; h < 2; h++) {
            int grow = row0 + mw * 32 + mi * 16 + r + h * 8;
#pragma unroll
            for (int nj = 0; nj < 12; nj++) {
                int ncol = nw * 96 + nj * 8 + cc;
                __half* dst = (ncol < 64) ? g_Q : (ncol < 128) ? g_K : g_V;
                int colw = ncol & 63;
                __half2 v = __floats2half2_rn(acc[mi][nj][2 * h] + biasv[nj].x,
                                              acc[mi][nj][2 * h + 1] + biasv[nj].y);
                *reinterpret_cast<__half2*>(&dst[(size_t)grow * HEAD + colw]) = v;
            }
        }
    }
}

// ---------------------------------------------------------------------------
// Kernel 2: split-K HMMA flash attention.
// grid (SEQ/64, BATCH, NSPLIT), 128 threads. Each block: 64 queries x 1024 keys.
// No max-subtraction softmax => partials (O, lsum) just add across splits.
// ---------------------------------------------------------------------------
#define BM 64
#define BN 128
#define NT2 (KSPLIT / BN)
#define OFF_Q   0
#define OFF_K0  8192
#define OFF_K1  24576
#define OFF_V0  40960
#define OFF_V1  57344
#define ATTN_SMEM 73728

__global__ __launch_bounds__(128, 3) void attn_split_kernel()
{
    extern __shared__ char sm[];
    const uint32_t sb = smem_u32(sm);
    const int tid  = threadIdx.x;
    const int lane = tid & 31;
    const int warp = tid >> 5;
    const int b    = blockIdx.y;
    const int q0   = blockIdx.x * BM;
    const int sp   = blockIdx.z;
    const int kb0  = sp * KSPLIT;
    const int qb   = warp * 16;

    const uint32_t sQ = sb + OFF_Q;
    const uint32_t sK[2] = { sb + OFF_K0, sb + OFF_K1 };
    const uint32_t sV[2] = { sb + OFF_V0, sb + OFF_V1 };

    auto issue_rows8 = [&](uint32_t dstbase, const __half* src, int row0g) {
#pragma unroll
        for (int i = 0; i < 8; i++) {
            int c   = tid + 128 * i;
            int row = c >> 3, c16 = c & 7;
            uint32_t dst = dstbase + row * 128 +
                (((uint32_t)(c16 * 16)) ^ (((uint32_t)(row & 7)) << 4));
            CP16(dst, src + (size_t)(row0g + row) * HEAD + c16 * 8);
        }
    };
    auto issue_rows4 = [&](uint32_t dstbase, const __half* src, int row0g) {
#pragma unroll
        for (int i = 0; i < 4; i++) {
            int c   = tid + 128 * i;
            int row = c >> 3, c16 = c & 7;
            uint32_t dst = dstbase + row * 128 +
                (((uint32_t)(c16 * 16)) ^ (((uint32_t)(row & 7)) << 4));
            CP16(dst, src + (size_t)(row0g + row) * HEAD + c16 * 8);
        }
    };

    issue_rows4(sQ, g_Q, b * SEQ + q0);
    issue_rows8(sK[0], g_K, b * SEQ + kb0);
    issue_rows8(sV[0], g_V, b * SEQ + kb0);
    CP_COMMIT();

    const int g = lane >> 3, li = lane & 7;

    uint32_t qf[4][4];
    float    O[8][4];
#pragma unroll
    for (int n = 0; n < 8; n++)
#pragma unroll
        for (int i = 0; i < 4; i++) O[n][i] = 0.f;
    float lsum0 = 0.f, lsum1 = 0.f;

    for (int t = 0; t < NT2; t++) {
        if (t + 1 < NT2) {
            issue_rows8(sK[(t + 1) & 1], g_K, b * SEQ + kb0 + (t + 1) * BN);
            issue_rows8(sV[(t + 1) & 1], g_V, b * SEQ + kb0 + (t + 1) * BN);
            CP_COMMIT();
            asm volatile("cp.async.wait_group 1;" ::: "memory");
        } else {
            asm volatile("cp.async.wait_group 0;" ::: "memory");
        }
        __syncthreads();

        if (t == 0) {
#pragma unroll
            for (int kk = 0; kk < 4; kk++) {
                int row  = qb + (g & 1) * 8 + li;
                int colh = kk * 16 + (g >> 1) * 8;
                ldsm_x4(qf[kk], sw_addr(sQ, row, colh));
            }
        }

        const uint32_t kbuf = sK[t & 1], vbuf = sV[t & 1];

#pragma unroll
        for (int j = 0; j < 8; j++) {
            float s0[4] = {0.f, 0.f, 0.f, 0.f};
            float s1[4] = {0.f, 0.f, 0.f, 0.f};
#pragma unroll
            for (int kk = 0; kk < 4; kk++) {
                uint32_t kbv[4];
                int row  = j * 16 + (g >> 1) * 8 + li;
                int colh = kk * 16 + (g & 1) * 8;
                ldsm_x4(kbv, sw_addr(kbuf, row, colh));
                mma16816(s0, qf[kk], &kbv[0]);
                mma16816(s1, qf[kk], &kbv[2]);
            }

            float e00 = ex2f(s0[0]);
            float e01 = ex2f(s0[1]);
            float e02 = ex2f(s0[2]);
            float e03 = ex2f(s0[3]);
            float e10 = ex2f(s1[0]);
            float e11 = ex2f(s1[1]);
            float e12 = ex2f(s1[2]);
            float e13 = ex2f(s1[3]);
            lsum0 += (e00 + e01) + (e10 + e11);
            lsum1 += (e02 + e03) + (e12 + e13);

            uint32_t pa[4];
            __half2 h;
            h = __floats2half2_rn(e00, e01); pa[0] = *reinterpret_cast<uint32_t*>(&h);
            h = __floats2half2_rn(e02, e03); pa[1] = *reinterpret_cast<uint32_t*>(&h);
            h = __floats2half2_rn(e10, e11); pa[2] = *reinterpret_cast<uint32_t*>(&h);
            h = __floats2half2_rn(e12, e13); pa[3] = *reinterpret_cast<uint32_t*>(&h);

#pragma unroll
            for (int p = 0; p < 4; p++) {
                uint32_t vb[4];
                int row  = j * 16 + (g & 1) * 8 + li;
                int colh = p * 16 + (g >> 1) * 8;
                ldsm_x4_t(vb, sw_addr(vbuf, row, colh));
                mma16816(O[2 * p],     pa, &vb[0]);
                mma16816(O[2 * p + 1], pa, &vb[2]);
            }
        }
        __syncthreads();
    }

    // reduce lsum across quad; write partials (unnormalized)
    lsum0 += __shfl_xor_sync(0xffffffffu, lsum0, 1);
    lsum0 += __shfl_xor_sync(0xffffffffu, lsum0, 2);
    lsum1 += __shfl_xor_sync(0xffffffffu, lsum1, 1);
    lsum1 += __shfl_xor_sync(0xffffffffu, lsum1, 2);

    const int r  = lane >> 2;
    const int cc = (lane & 3) * 2;
    const int grow0 = b * SEQ + q0 + qb + r;
    if ((lane & 3) == 0) {
        g_Lpart[sp * NROW + grow0]     = lsum0;
        g_Lpart[sp * NROW + grow0 + 8] = lsum1;
    }
    float* op = g_Opart + (size_t)sp * NROW * HEAD;
    float* row0p = op + (size_t)grow0 * HEAD;
    float* row1p = op + (size_t)(grow0 + 8) * HEAD;
#pragma unroll
    for (int nb = 0; nb < 8; nb++) {
        *reinterpret_cast<float2*>(row0p + nb * 8 + cc) = make_float2(O[nb][0], O[nb][1]);
        *reinterpret_cast<float2*>(row1p + nb * 8 + cc) = make_float2(O[nb][2], O[nb][3]);
    }
}

// ---------------------------------------------------------------------------
// Kernel 3: combine splits: out = (O0 + O1) / (l0 + l1).
// 262144 float4s, grid 1024 x 256.
// ---------------------------------------------------------------------------
__global__ __launch_bounds__(256) void combine_kernel(float* __restrict__ out)
{
    int idx = blockIdx.x * 256 + threadIdx.x;   // float4 index
    int row = idx >> 4;
    float l = g_Lpart[row] + g_Lpart[NROW + row];
    float inv = 1.f / l;
    const float4* p0 = reinterpret_cast<const float4*>(g_Opart);
    const float4* p1 = reinterpret_cast<const float4*>(g_Opart + (size_t)NROW * HEAD);
    float4 a = p0[idx];
    float4 b = p1[idx];
    float4 o = make_float4((a.x + b.x) * inv, (a.y + b.y) * inv,
                           (a.z + b.z) * inv, (a.w + b.w) * inv);
    reinterpret_cast<float4*>(out)[idx] = o;
}

// ---------------------------------------------------------------------------
extern "C" void kernel_launch(void* const* d_in, const int* in_sizes, int n_in,
                              void* d_out, int out_size)
{
    const float* x  = (const float*)d_in[0];
    const float* Wq = (const float*)d_in[1];
    const float* bq = (const float*)d_in[2];
    const float* Wk = (const float*)d_in[3];
    const float* bk = (const float*)d_in[4];
    const float* Wv = (const float*)d_in[5];
    const float* bv = (const float*)d_in[6];
    float* out = (float*)d_out;

    wsplit_kernel<<<dim3(24, 3), 256>>>(Wq, Wk, Wv);

    cudaFuncSetAttribute(qkv_hmma_kernel,
                         cudaFuncAttributeMaxDynamicSharedMemorySize, PROJ_SMEM);
    qkv_hmma_kernel<<<NROW / 128, 256, PROJ_SMEM>>>(x, bq, bk, bv);

    cudaFuncSetAttribute(attn_split_kernel,
                         cudaFuncAttributeMaxDynamicSharedMemorySize, ATTN_SMEM);
    attn_split_kernel<<<dim3(SEQ / BM, BATCH, NSPLIT), 128, ATTN_SMEM>>>();

    combine_kernel<<<(NROW * HEAD / 4) / 256, 256>>>(out);
}

// round 10
// speedup vs baseline: 1.1090x; 1.1033x over previous
#include <cuda_runtime.h>
#include <cuda_fp16.h>
#include <cstdint>

#define D_MODEL 768
#define HEAD    64
#define BATCH   8
#define SEQ     2048
#define NROW    (BATCH * SEQ)

// Scale folded into Q: scores come out in log2 domain.
#define QSC 0.1803368801111244f   // 0.125 * log2(e)

// Scratch (no device allocation allowed).
__device__ __half g_Q[NROW * HEAD];
__device__ __half g_K[NROW * HEAD];
__device__ __half g_V[NROW * HEAD];
__device__ __half g_Wth[192 * D_MODEL];   // W^T fp16 [n][k] (Wq pre-scaled)

// ---------------------------------------------------------------------------
// common helpers
// ---------------------------------------------------------------------------
__device__ __forceinline__ uint32_t smem_u32(const void* p) {
    uint32_t a;
    asm("{ .reg .u64 t; cvta.to.shared.u64 t, %1; cvt.u32.u64 %0, t; }"
        : "=r"(a) : "l"(p));
    return a;
}
// 128B rows
__device__ __forceinline__ uint32_t sw_addr(uint32_t base, int row, int colh) {
    return base + row * 128 + (((uint32_t)(colh * 2)) ^ (((uint32_t)(row & 7)) << 4));
}
__device__ __forceinline__ void ldsm_x4(uint32_t* r, uint32_t addr) {
    asm volatile("ldmatrix.sync.aligned.m8n8.x4.shared.b16 {%0,%1,%2,%3}, [%4];"
                 : "=r"(r[0]), "=r"(r[1]), "=r"(r[2]), "=r"(r[3]) : "r"(addr));
}
__device__ __forceinline__ void ldsm_x4_t(uint32_t* r, uint32_t addr) {
    asm volatile("ldmatrix.sync.aligned.m8n8.x4.trans.shared.b16 {%0,%1,%2,%3}, [%4];"
                 : "=r"(r[0]), "=r"(r[1]), "=r"(r[2]), "=r"(r[3]) : "r"(addr));
}
__device__ __forceinline__ void mma16816(float* d, const uint32_t* a, const uint32_t* b) {
    asm volatile(
        "mma.sync.aligned.m16n8k16.row.col.f32.f16.f16.f32 "
        "{%0,%1,%2,%3}, {%4,%5,%6,%7}, {%8,%9}, {%0,%1,%2,%3};"
        : "+f"(d[0]), "+f"(d[1]), "+f"(d[2]), "+f"(d[3])
        : "r"(a[0]), "r"(a[1]), "r"(a[2]), "r"(a[3]), "r"(b[0]), "r"(b[1]));
}
__device__ __forceinline__ float ex2f(float x) {
    float y;
    asm("ex2.approx.f32 %0, %1;" : "=f"(y) : "f"(x));
    return y;
}
#define CP16(dst, src) \
    asm volatile("cp.async.cg.shared.global [%0], [%1], 16;" \
                 :: "r"(dst), "l"(src) : "memory")
#define CP_COMMIT() asm volatile("cp.async.commit_group;" ::: "memory")

// ---------------------------------------------------------------------------
// Kernel 0: W transpose + fp16 convert -> g_Wth [n][k] (Wq scaled by QSC).
// grid (24, 3): 32-k x 64-n tiles, 256 threads, vectorized.
// ---------------------------------------------------------------------------
__global__ __launch_bounds__(256) void wsplit_kernel(
    const float* __restrict__ Wq, const float* __restrict__ Wk,
    const float* __restrict__ Wv)
{
    __shared__ float tile[32][65];
    const float* W = (blockIdx.y == 0) ? Wq : (blockIdx.y == 1) ? Wk : Wv;
    const float sc = (blockIdx.y == 0) ? QSC : 1.0f;
    const int kbase = blockIdx.x * 32;
    const int tid = threadIdx.x;
#pragma unroll
    for (int i = 0; i < 2; i++) {
        int f4 = tid + 256 * i;
        int k = f4 >> 4, c4 = f4 & 15;
        float4 v = *reinterpret_cast<const float4*>(&W[(size_t)(kbase + k) * 64 + c4 * 4]);
        tile[k][c4 * 4 + 0] = v.x;
        tile[k][c4 * 4 + 1] = v.y;
        tile[k][c4 * 4 + 2] = v.z;
        tile[k][c4 * 4 + 3] = v.w;
    }
    __syncthreads();
#pragma unroll
    for (int j = 0; j < 4; j++) {
        int idx = tid + 256 * j;
        int n = idx >> 4, kp = idx & 15;
        __half2 h = __floats2half2_rn(tile[2 * kp][n] * sc, tile[2 * kp + 1][n] * sc);
        *reinterpret_cast<__half2*>(
            &g_Wth[(size_t)(blockIdx.y * 64 + n) * D_MODEL + kbase + 2 * kp]) = h;
    }
}

// ---------------------------------------------------------------------------
// Kernel 1: HMMA QKV projection (round-5 proven structure).
// C[16384,192] = Xh · Wh (fp32 accumulate). BM=128, N=192, BK=64.
// ---------------------------------------------------------------------------
#define NCHUNK (D_MODEL / 64)
#define PXH 0
#define PWH0 16384
#define PWH1 40960
#define PROJ_SMEM 65536

__global__ __launch_bounds__(256, 1) void qkv_hmma_kernel(
    const float* __restrict__ x,
    const float* __restrict__ bq, const float* __restrict__ bk,
    const float* __restrict__ bv)
{
    extern __shared__ char sm[];
    const uint32_t sb = smem_u32(sm);
    const int tid  = threadIdx.x;
    const int lane = tid & 31;
    const int warp = tid >> 5;
    const int g    = lane >> 3, li = lane & 7;
    const int mw   = warp >> 1;
    const int nw   = warp & 1;
    const int row0 = blockIdx.x * 128;

    const uint32_t sWH[2] = { sb + PWH0, sb + PWH1 };

    auto issue_w = [&](int c) {
#pragma unroll
        for (int i = 0; i < 6; i++) {
            int idx = tid + 256 * i;
            int n = idx >> 3, c16 = idx & 7;
            uint32_t off = n * 128 + (((uint32_t)(c16 * 16)) ^ (((uint32_t)(n & 7)) << 4));
            CP16(sWH[c & 1] + off, g_Wth + (size_t)n * D_MODEL + c * 64 + c16 * 8);
        }
    };

    float xr[32];
    auto ldg_x = [&](int c) {
#pragma unroll
        for (int i = 0; i < 8; i++) {
            int f = tid + 256 * i;
            int r = f >> 4, c4 = f & 15;
            float4 v = *reinterpret_cast<const float4*>(
                &x[(size_t)(row0 + r) * D_MODEL + c * 64 + c4 * 4]);
            xr[4 * i] = v.x; xr[4 * i + 1] = v.y; xr[4 * i + 2] = v.z; xr[4 * i + 3] = v.w;
        }
    };

    issue_w(0); CP_COMMIT();
    ldg_x(0);

    float acc[2][12][4];
#pragma unroll
    for (int mi = 0; mi < 2; mi++)
#pragma unroll
        for (int nj = 0; nj < 12; nj++)
#pragma unroll
            for (int i = 0; i < 4; i++) acc[mi][nj][i] = 0.f;

    for (int c = 0; c < NCHUNK; c++) {
        __syncthreads();
#pragma unroll
        for (int i = 0; i < 8; i++) {
            int f = tid + 256 * i;
            int r = f >> 4, c4 = f & 15;
            __half2 h0 = __floats2half2_rn(xr[4 * i],     xr[4 * i + 1]);
            __half2 h1 = __floats2half2_rn(xr[4 * i + 2], xr[4 * i + 3]);
            uint32_t off = r * 128 + (((uint32_t)(c4 * 8)) ^ (((uint32_t)(r & 7)) << 4));
            uint2 hv = make_uint2(*reinterpret_cast<uint32_t*>(&h0),
                                  *reinterpret_cast<uint32_t*>(&h1));
            *reinterpret_cast<uint2*>(sm + PXH + off) = hv;
        }
        if (c + 1 < NCHUNK) {
            issue_w(c + 1); CP_COMMIT();
            asm volatile("cp.async.wait_group 1;" ::: "memory");
        } else {
            asm volatile("cp.async.wait_group 0;" ::: "memory");
        }
        __syncthreads();
        if (c + 1 < NCHUNK) ldg_x(c + 1);

        const uint32_t whb = sWH[c & 1];
#pragma unroll
        for (int kk = 0; kk < 4; kk++) {
            uint32_t ah[2][4];
#pragma unroll
            for (int mi = 0; mi < 2; mi++) {
                int row  = mw * 32 + mi * 16 + (g & 1) * 8 + li;
                int colh = kk * 16 + (g >> 1) * 8;
                ldsm_x4(ah[mi], sw_addr(sb + PXH, row, colh));
            }
#pragma unroll
            for (int nj = 0; nj < 6; nj++) {
                uint32_t bh[4];
                int nrow = nw * 96 + nj * 16 + (g >> 1) * 8 + li;
                int colh = kk * 16 + (g & 1) * 8;
                ldsm_x4(bh, sw_addr(whb, nrow, colh));
#pragma unroll
                for (int mi = 0; mi < 2; mi++) {
                    mma16816(acc[mi][2 * nj],     ah[mi], &bh[0]);
                    mma16816(acc[mi][2 * nj + 1], ah[mi], &bh[2]);
                }
            }
        }
    }

    const int r  = lane >> 2;
    const int cc = (lane & 3) * 2;
    float2 biasv[12];
#pragma unroll
    for (int nj = 0; nj < 12; nj++) {
        int ncol = nw * 96 + nj * 8 + cc;
        const float* bp = (ncol < 64) ? bq : (ncol < 128) ? bk : bv;
        float s = (ncol < 64) ? QSC : 1.0f;
        int colw = ncol & 63;
        biasv[nj] = make_float2(bp[colw] * s, bp[colw + 1] * s);
    }
#pragma unroll
    for (int mi = 0; mi < 2; mi++) {
#pragma unroll
        for (int h = 0; h < 2; h++) {
            int grow = row0 + mw * 32 + mi * 16 + r + h * 8;
#pragma unroll
            for (int nj = 0; nj < 12; nj++) {
                int ncol = nw * 96 + nj * 8 + cc;
                __half* dst = (ncol < 64) ? g_Q : (ncol < 128) ? g_K : g_V;
                int colw = ncol & 63;
                __half2 v = __floats2half2_rn(acc[mi][nj][2 * h] + biasv[nj].x,
                                              acc[mi][nj][2 * h + 1] + biasv[nj].y);
                *reinterpret_cast<__half2*>(&dst[(size_t)grow * HEAD + colw]) = v;
            }
        }
    }
}

// ---------------------------------------------------------------------------
// Kernel 2: HMMA flash attention, 8 warps, intra-block slab split.
// BM=64 queries, BN=128 keys/tile. Warp w: qgroup = w&3 (16 q rows),
// kgroup = w>>2 (slabs 0-3 or 4-7 of each tile). Partials merged in smem.
// grid (SEQ/64, BATCH) = 256 blocks; __launch_bounds__(256,2) -> 2 blocks/SM.
// ---------------------------------------------------------------------------
#define BM 64
#define BN 128
#define NT (SEQ / BN)
#define OFF_Q   0
#define OFF_K0  8192
#define OFF_K1  24576
#define OFF_V0  40960
#define OFF_V1  57344
#define ATTN_SMEM 73728

__global__ __launch_bounds__(256, 2) void attn_hmma_kernel(float* __restrict__ out)
{
    extern __shared__ char sm[];
    const uint32_t sb = smem_u32(sm);
    const int tid  = threadIdx.x;
    const int lane = tid & 31;
    const int warp = tid >> 5;
    const int qw   = warp & 3;        // q-group (16 rows)
    const int kg   = warp >> 2;       // slab half (0: j=0..3, 1: j=4..7)
    const int b    = blockIdx.y;
    const int q0   = blockIdx.x * BM;
    const int qb   = qw * 16;

    const uint32_t sQ = sb + OFF_Q;
    const uint32_t sK[2] = { sb + OFF_K0, sb + OFF_K1 };
    const uint32_t sV[2] = { sb + OFF_V0, sb + OFF_V1 };

    // loaders: 256 threads. K/V tile = 1024 16B chunks, Q tile = 512.
    auto issue_rows8 = [&](uint32_t dstbase, const __half* src, int row0g) {
#pragma unroll
        for (int i = 0; i < 4; i++) {
            int c   = tid + 256 * i;
            int row = c >> 3, c16 = c & 7;
            uint32_t dst = dstbase + row * 128 +
                (((uint32_t)(c16 * 16)) ^ (((uint32_t)(row & 7)) << 4));
            CP16(dst, src + (size_t)(row0g + row) * HEAD + c16 * 8);
        }
    };
    auto issue_rows4 = [&](uint32_t dstbase, const __half* src, int row0g) {
#pragma unroll
        for (int i = 0; i < 2; i++) {
            int c   = tid + 256 * i;
            int row = c >> 3, c16 = c & 7;
            uint32_t dst = dstbase + row * 128 +
                (((uint32_t)(c16 * 16)) ^ (((uint32_t)(row & 7)) << 4));
            CP16(dst, src + (size_t)(row0g + row) * HEAD + c16 * 8);
        }
    };

    issue_rows4(sQ, g_Q, b * SEQ + q0);
    issue_rows8(sK[0], g_K, b * SEQ);
    issue_rows8(sV[0], g_V, b * SEQ);
    CP_COMMIT();

    const int g = lane >> 3, li = lane & 7;

    uint32_t qf[4][4];
    float    O[8][4];
#pragma unroll
    for (int n = 0; n < 8; n++)
#pragma unroll
        for (int i = 0; i < 4; i++) O[n][i] = 0.f;
    float lsum0 = 0.f, lsum1 = 0.f;

    for (int t = 0; t < NT; t++) {
        if (t + 1 < NT) {
            issue_rows8(sK[(t + 1) & 1], g_K, b * SEQ + (t + 1) * BN);
            issue_rows8(sV[(t + 1) & 1], g_V, b * SEQ + (t + 1) * BN);
            CP_COMMIT();
            asm volatile("cp.async.wait_group 1;" ::: "memory");
        } else {
            asm volatile("cp.async.wait_group 0;" ::: "memory");
        }
        __syncthreads();

        if (t == 0) {
#pragma unroll
            for (int kk = 0; kk < 4; kk++) {
                int row  = qb + (g & 1) * 8 + li;
                int colh = kk * 16 + (g >> 1) * 8;
                ldsm_x4(qf[kk], sw_addr(sQ, row, colh));
            }
        }

        const uint32_t kbuf = sK[t & 1], vbuf = sV[t & 1];

        // this warp's 4 slabs (16 keys each)
#pragma unroll
        for (int jj = 0; jj < 4; jj++) {
            const int j = kg * 4 + jj;
            float s0[4] = {0.f, 0.f, 0.f, 0.f};
            float s1[4] = {0.f, 0.f, 0.f, 0.f};
#pragma unroll
            for (int kk = 0; kk < 4; kk++) {
                uint32_t kbv[4];
                int row  = j * 16 + (g >> 1) * 8 + li;
                int colh = kk * 16 + (g & 1) * 8;
                ldsm_x4(kbv, sw_addr(kbuf, row, colh));
                mma16816(s0, qf[kk], &kbv[0]);
                mma16816(s1, qf[kk], &kbv[2]);
            }

            float e00 = ex2f(s0[0]);
            float e01 = ex2f(s0[1]);
            float e02 = ex2f(s0[2]);
            float e03 = ex2f(s0[3]);
            float e10 = ex2f(s1[0]);
            float e11 = ex2f(s1[1]);
            float e12 = ex2f(s1[2]);
            float e13 = ex2f(s1[3]);
            lsum0 += (e00 + e01) + (e10 + e11);
            lsum1 += (e02 + e03) + (e12 + e13);

            uint32_t pa[4];
            __half2 h;
            h = __floats2half2_rn(e00, e01); pa[0] = *reinterpret_cast<uint32_t*>(&h);
            h = __floats2half2_rn(e02, e03); pa[1] = *reinterpret_cast<uint32_t*>(&h);
            h = __floats2half2_rn(e10, e11); pa[2] = *reinterpret_cast<uint32_t*>(&h);
            h = __floats2half2_rn(e12, e13); pa[3] = *reinterpret_cast<uint32_t*>(&h);

#pragma unroll
            for (int p = 0; p < 4; p++) {
                uint32_t vb[4];
                int row  = j * 16 + (g & 1) * 8 + li;
                int colh = p * 16 + (g >> 1) * 8;
                ldsm_x4_t(vb, sw_addr(vbuf, row, colh));
                mma16816(O[2 * p],     pa, &vb[0]);
                mma16816(O[2 * p + 1], pa, &vb[2]);
            }
        }
        __syncthreads();
    }

    // reduce lsum across quad
    lsum0 += __shfl_xor_sync(0xffffffffu, lsum0, 1);
    lsum0 += __shfl_xor_sync(0xffffffffu, lsum0, 2);
    lsum1 += __shfl_xor_sync(0xffffffffu, lsum1, 1);
    lsum1 += __shfl_xor_sync(0xffffffffu, lsum1, 2);

    // merge warp-group partials via smem (reuse K buffers; loop is done)
    float* sO1 = reinterpret_cast<float*>(sm + OFF_K0);         // [64][64]
    float* sL1 = reinterpret_cast<float*>(sm + OFF_K0 + 16384); // [64]

    const int r  = lane >> 2;
    const int cc = (lane & 3) * 2;
    if (kg == 1) {
        int lr0 = qb + r, lr1 = qb + r + 8;
#pragma unroll
        for (int nb = 0; nb < 8; nb++) {
            sO1[lr0 * 64 + nb * 8 + cc]     = O[nb][0];
            sO1[lr0 * 64 + nb * 8 + cc + 1] = O[nb][1];
            sO1[lr1 * 64 + nb * 8 + cc]     = O[nb][2];
            sO1[lr1 * 64 + nb * 8 + cc + 1] = O[nb][3];
        }
        if ((lane & 3) == 0) { sL1[lr0] = lsum0; sL1[lr1] = lsum1; }
    }
    __syncthreads();
    if (kg == 0) {
        int lr0 = qb + r, lr1 = qb + r + 8;
        float inv0 = 1.f / (lsum0 + sL1[lr0]);
        float inv1 = 1.f / (lsum1 + sL1[lr1]);
        float* row0p = &out[(size_t)(b * SEQ + q0 + lr0) * HEAD];
        float* row1p = &out[(size_t)(b * SEQ + q0 + lr1) * HEAD];
#pragma unroll
        for (int nb = 0; nb < 8; nb++) {
            float2 v0 = make_float2((O[nb][0] + sO1[lr0 * 64 + nb * 8 + cc])     * inv0,
                                    (O[nb][1] + sO1[lr0 * 64 + nb * 8 + cc + 1]) * inv0);
            float2 v1 = make_float2((O[nb][2] + sO1[lr1 * 64 + nb * 8 + cc])     * inv1,
                                    (O[nb][3] + sO1[lr1 * 64 + nb * 8 + cc + 1]) * inv1);
            *reinterpret_cast<float2*>(row0p + nb * 8 + cc) = v0;
            *reinterpret_cast<float2*>(row1p + nb * 8 + cc) = v1;
        }
    }
}

// ---------------------------------------------------------------------------
extern "C" void kernel_launch(void* const* d_in, const int* in_sizes, int n_in,
                              void* d_out, int out_size)
{
    const float* x  = (const float*)d_in[0];
    const float* Wq = (const float*)d_in[1];
    const float* bq = (const float*)d_in[2];
    const float* Wk = (const float*)d_in[3];
    const float* bk = (const float*)d_in[4];
    const float* Wv = (const float*)d_in[5];
    const float* bv = (const float*)d_in[6];
    float* out = (float*)d_out;

    wsplit_kernel<<<dim3(24, 3), 256>>>(Wq, Wk, Wv);

    cudaFuncSetAttribute(qkv_hmma_kernel,
                         cudaFuncAttributeMaxDynamicSharedMemorySize, PROJ_SMEM);
    qkv_hmma_kernel<<<NROW / 128, 256, PROJ_SMEM>>>(x, bq, bk, bv);

    cudaFuncSetAttribute(attn_hmma_kernel,
                         cudaFuncAttributeMaxDynamicSharedMemorySize, ATTN_SMEM);
    attn_hmma_kernel<<<dim3(SEQ / BM, BATCH), 256, ATTN_SMEM>>>(out);
}

// round 11
// speedup vs baseline: 1.1103x; 1.0011x over previous
#include <cuda_runtime.h>
#include <cuda_fp16.h>
#include <cstdint>

#define D_MODEL 768
#define HEAD    64
#define BATCH   8
#define SEQ     2048
#define NROW    (BATCH * SEQ)

// Scale folded into Q: scores come out in log2 domain.
#define QSC 0.1803368801111244f   // 0.125 * log2(e)

// Scratch (no device allocation allowed).
__device__ __half g_Q[NROW * HEAD];
__device__ __half g_K[NROW * HEAD];
__device__ __half g_V[NROW * HEAD];
__device__ __half g_Wth[192 * D_MODEL];   // W^T fp16 [n][k] (Wq pre-scaled)

// ---------------------------------------------------------------------------
// common helpers
// ---------------------------------------------------------------------------
__device__ __forceinline__ uint32_t smem_u32(const void* p) {
    uint32_t a;
    asm("{ .reg .u64 t; cvta.to.shared.u64 t, %1; cvt.u32.u64 %0, t; }"
        : "=r"(a) : "l"(p));
    return a;
}
// 128B rows
__device__ __forceinline__ uint32_t sw_addr(uint32_t base, int row, int colh) {
    return base + row * 128 + (((uint32_t)(colh * 2)) ^ (((uint32_t)(row & 7)) << 4));
}
__device__ __forceinline__ void ldsm_x4(uint32_t* r, uint32_t addr) {
    asm volatile("ldmatrix.sync.aligned.m8n8.x4.shared.b16 {%0,%1,%2,%3}, [%4];"
                 : "=r"(r[0]), "=r"(r[1]), "=r"(r[2]), "=r"(r[3]) : "r"(addr));
}
__device__ __forceinline__ void ldsm_x4_t(uint32_t* r, uint32_t addr) {
    asm volatile("ldmatrix.sync.aligned.m8n8.x4.trans.shared.b16 {%0,%1,%2,%3}, [%4];"
                 : "=r"(r[0]), "=r"(r[1]), "=r"(r[2]), "=r"(r[3]) : "r"(addr));
}
__device__ __forceinline__ void mma16816(float* d, const uint32_t* a, const uint32_t* b) {
    asm volatile(
        "mma.sync.aligned.m16n8k16.row.col.f32.f16.f16.f32 "
        "{%0,%1,%2,%3}, {%4,%5,%6,%7}, {%8,%9}, {%0,%1,%2,%3};"
        : "+f"(d[0]), "+f"(d[1]), "+f"(d[2]), "+f"(d[3])
        : "r"(a[0]), "r"(a[1]), "r"(a[2]), "r"(a[3]), "r"(b[0]), "r"(b[1]));
}
__device__ __forceinline__ float ex2f(float x) {
    float y;
    asm("ex2.approx.f32 %0, %1;" : "=f"(y) : "f"(x));
    return y;
}
#define CP16(dst, src) \
    asm volatile("cp.async.cg.shared.global [%0], [%1], 16;" \
                 :: "r"(dst), "l"(src) : "memory")
#define CP_COMMIT() asm volatile("cp.async.commit_group;" ::: "memory")

// ---------------------------------------------------------------------------
// Kernel 0: W transpose + fp16 convert -> g_Wth [n][k] (Wq scaled by QSC).
// grid (24, 3): 32-k x 64-n tiles, 256 threads, vectorized.
// ---------------------------------------------------------------------------
__global__ __launch_bounds__(256) void wsplit_kernel(
    const float* __restrict__ Wq, const float* __restrict__ Wk,
    const float* __restrict__ Wv)
{
    __shared__ float tile[32][65];
    const float* W = (blockIdx.y == 0) ? Wq : (blockIdx.y == 1) ? Wk : Wv;
    const float sc = (blockIdx.y == 0) ? QSC : 1.0f;
    const int kbase = blockIdx.x * 32;
    const int tid = threadIdx.x;
#pragma unroll
    for (int i = 0; i < 2; i++) {
        int f4 = tid + 256 * i;
        int k = f4 >> 4, c4 = f4 & 15;
        float4 v = *reinterpret_cast<const float4*>(&W[(size_t)(kbase + k) * 64 + c4 * 4]);
        tile[k][c4 * 4 + 0] = v.x;
        tile[k][c4 * 4 + 1] = v.y;
        tile[k][c4 * 4 + 2] = v.z;
        tile[k][c4 * 4 + 3] = v.w;
    }
    __syncthreads();
#pragma unroll
    for (int j = 0; j < 4; j++) {
        int idx = tid + 256 * j;
        int n = idx >> 4, kp = idx & 15;
        __half2 h = __floats2half2_rn(tile[2 * kp][n] * sc, tile[2 * kp + 1][n] * sc);
        *reinterpret_cast<__half2*>(
            &g_Wth[(size_t)(blockIdx.y * 64 + n) * D_MODEL + kbase + 2 * kp]) = h;
    }
}

// ---------------------------------------------------------------------------
// Kernel 1: HMMA QKV projection (round-5 proven structure).
// C[16384,192] = Xh · Wh (fp32 accumulate). BM=128, N=192, BK=64.
// ---------------------------------------------------------------------------
#define NCHUNK (D_MODEL / 64)
#define PXH 0
#define PWH0 16384
#define PWH1 40960
#define PROJ_SMEM 65536

__global__ __launch_bounds__(256, 1) void qkv_hmma_kernel(
    const float* __restrict__ x,
    const float* __restrict__ bq, const float* __restrict__ bk,
    const float* __restrict__ bv)
{
    extern __shared__ char sm[];
    const uint32_t sb = smem_u32(sm);
    const int tid  = threadIdx.x;
    const int lane = tid & 31;
    const int warp = tid >> 5;
    const int g    = lane >> 3, li = lane & 7;
    const int mw   = warp >> 1;
    const int nw   = warp & 1;
    const int row0 = blockIdx.x * 128;

    const uint32_t sWH[2] = { sb + PWH0, sb + PWH1 };

    auto issue_w = [&](int c) {
#pragma unroll
        for (int i = 0; i < 6; i++) {
            int idx = tid + 256 * i;
            int n = idx >> 3, c16 = idx & 7;
            uint32_t off = n * 128 + (((uint32_t)(c16 * 16)) ^ (((uint32_t)(n & 7)) << 4));
            CP16(sWH[c & 1] + off, g_Wth + (size_t)n * D_MODEL + c * 64 + c16 * 8);
        }
    };

    float xr[32];
    auto ldg_x = [&](int c) {
#pragma unroll
        for (int i = 0; i < 8; i++) {
            int f = tid + 256 * i;
            int r = f >> 4, c4 = f & 15;
            float4 v = *reinterpret_cast<const float4*>(
                &x[(size_t)(row0 + r) * D_MODEL + c * 64 + c4 * 4]);
            xr[4 * i] = v.x; xr[4 * i + 1] = v.y; xr[4 * i + 2] = v.z; xr[4 * i + 3] = v.w;
        }
    };

    issue_w(0); CP_COMMIT();
    ldg_x(0);

    float acc[2][12][4];
#pragma unroll
    for (int mi = 0; mi < 2; mi++)
#pragma unroll
        for (int nj = 0; nj < 12; nj++)
#pragma unroll
            for (int i = 0; i < 4; i++) acc[mi][nj][i] = 0.f;

    for (int c = 0; c < NCHUNK; c++) {
        __syncthreads();
#pragma unroll
        for (int i = 0; i < 8; i++) {
            int f = tid + 256 * i;
            int r = f >> 4, c4 = f & 15;
            __half2 h0 = __floats2half2_rn(xr[4 * i],     xr[4 * i + 1]);
            __half2 h1 = __floats2half2_rn(xr[4 * i + 2], xr[4 * i + 3]);
            uint32_t off = r * 128 + (((uint32_t)(c4 * 8)) ^ (((uint32_t)(r & 7)) << 4));
            uint2 hv = make_uint2(*reinterpret_cast<uint32_t*>(&h0),
                                  *reinterpret_cast<uint32_t*>(&h1));
            *reinterpret_cast<uint2*>(sm + PXH + off) = hv;
        }
        if (c + 1 < NCHUNK) {
            issue_w(c + 1); CP_COMMIT();
            asm volatile("cp.async.wait_group 1;" ::: "memory");
        } else {
            asm volatile("cp.async.wait_group 0;" ::: "memory");
        }
        __syncthreads();
        if (c + 1 < NCHUNK) ldg_x(c + 1);

        const uint32_t whb = sWH[c & 1];
#pragma unroll
        for (int kk = 0; kk < 4; kk++) {
            uint32_t ah[2][4];
#pragma unroll
            for (int mi = 0; mi < 2; mi++) {
                int row  = mw * 32 + mi * 16 + (g & 1) * 8 + li;
                int colh = kk * 16 + (g >> 1) * 8;
                ldsm_x4(ah[mi], sw_addr(sb + PXH, row, colh));
            }
#pragma unroll
            for (int nj = 0; nj < 6; nj++) {
                uint32_t bh[4];
                int nrow = nw * 96 + nj * 16 + (g >> 1) * 8 + li;
                int colh = kk * 16 + (g & 1) * 8;
                ldsm_x4(bh, sw_addr(whb, nrow, colh));
#pragma unroll
                for (int mi = 0; mi < 2; mi++) {
                    mma16816(acc[mi][2 * nj],     ah[mi], &bh[0]);
                    mma16816(acc[mi][2 * nj + 1], ah[mi], &bh[2]);
                }
            }
        }
    }

    const int r  = lane >> 2;
    const int cc = (lane & 3) * 2;
    float2 biasv[12];
#pragma unroll
    for (int nj = 0; nj < 12; nj++) {
        int ncol = nw * 96 + nj * 8 + cc;
        const float* bp = (ncol < 64) ? bq : (ncol < 128) ? bk : bv;
        float s = (ncol < 64) ? QSC : 1.0f;
        int colw = ncol & 63;
        biasv[nj] = make_float2(bp[colw] * s, bp[colw + 1] * s);
    }
#pragma unroll
    for (int mi = 0; mi < 2; mi++) {
#pragma unroll
        for (int h = 0; h < 2; h++) {
            int grow = row0 + mw * 32 + mi * 16 + r + h * 8;
#pragma unroll
            for (int nj = 0; nj < 12; nj++) {
                int ncol = nw * 96 + nj * 8 + cc;
                __half* dst = (ncol < 64) ? g_Q : (ncol < 128) ? g_K : g_V;
                int colw = ncol & 63;
                __half2 v = __floats2half2_rn(acc[mi][nj][2 * h] + biasv[nj].x,
                                              acc[mi][nj][2 * h + 1] + biasv[nj].y);
                *reinterpret_cast<__half2*>(&dst[(size_t)grow * HEAD + colw]) = v;
            }
        }
    }
}

// ---------------------------------------------------------------------------
// Kernel 2: HMMA flash attention, 8 warps, intra-block slab split.
// BM=64 queries, BN=128 keys/tile. Warp w: qgroup = w&3 (16 q rows),
// kgroup = w>>2 (slabs 0-3 or 4-7 of each tile). Partials merged in smem.
// grid (SEQ/64, BATCH) = 256 blocks; __launch_bounds__(256,2) -> 2 blocks/SM.
// ---------------------------------------------------------------------------
#define BM 64
#define BN 128
#define NT (SEQ / BN)
#define OFF_Q   0
#define OFF_K0  8192
#define OFF_K1  24576
#define OFF_V0  40960
#define OFF_V1  57344
#define ATTN_SMEM 73728

__global__ __launch_bounds__(256, 2) void attn_hmma_kernel(float* __restrict__ out)
{
    extern __shared__ char sm[];
    const uint32_t sb = smem_u32(sm);
    const int tid  = threadIdx.x;
    const int lane = tid & 31;
    const int warp = tid >> 5;
    const int qw   = warp & 3;        // q-group (16 rows)
    const int kg   = warp >> 2;       // slab half (0: j=0..3, 1: j=4..7)
    const int b    = blockIdx.y;
    const int q0   = blockIdx.x * BM;
    const int qb   = qw * 16;

    const uint32_t sQ = sb + OFF_Q;
    const uint32_t sK[2] = { sb + OFF_K0, sb + OFF_K1 };
    const uint32_t sV[2] = { sb + OFF_V0, sb + OFF_V1 };

    // loaders: 256 threads. K/V tile = 1024 16B chunks, Q tile = 512.
    auto issue_rows8 = [&](uint32_t dstbase, const __half* src, int row0g) {
#pragma unroll
        for (int i = 0; i < 4; i++) {
            int c   = tid + 256 * i;
            int row = c >> 3, c16 = c & 7;
            uint32_t dst = dstbase + row * 128 +
                (((uint32_t)(c16 * 16)) ^ (((uint32_t)(row & 7)) << 4));
            CP16(dst, src + (size_t)(row0g + row) * HEAD + c16 * 8);
        }
    };
    auto issue_rows4 = [&](uint32_t dstbase, const __half* src, int row0g) {
#pragma unroll
        for (int i = 0; i < 2; i++) {
            int c   = tid + 256 * i;
            int row = c >> 3, c16 = c & 7;
            uint32_t dst = dstbase + row * 128 +
                (((uint32_t)(c16 * 16)) ^ (((uint32_t)(row & 7)) << 4));
            CP16(dst, src + (size_t)(row0g + row) * HEAD + c16 * 8);
        }
    };

    issue_rows4(sQ, g_Q, b * SEQ + q0);
    issue_rows8(sK[0], g_K, b * SEQ);
    issue_rows8(sV[0], g_V, b * SEQ);
    CP_COMMIT();

    const int g = lane >> 3, li = lane & 7;

    uint32_t qf[4][4];
    float    O[8][4];
#pragma unroll
    for (int n = 0; n < 8; n++)
#pragma unroll
        for (int i = 0; i < 4; i++) O[n][i] = 0.f;
    float lsum0 = 0.f, lsum1 = 0.f;

    for (int t = 0; t < NT; t++) {
        if (t + 1 < NT) {
            issue_rows8(sK[(t + 1) & 1], g_K, b * SEQ + (t + 1) * BN);
            issue_rows8(sV[(t + 1) & 1], g_V, b * SEQ + (t + 1) * BN);
            CP_COMMIT();
            asm volatile("cp.async.wait_group 1;" ::: "memory");
        } else {
            asm volatile("cp.async.wait_group 0;" ::: "memory");
        }
        __syncthreads();

        if (t == 0) {
#pragma unroll
            for (int kk = 0; kk < 4; kk++) {
                int row  = qb + (g & 1) * 8 + li;
                int colh = kk * 16 + (g >> 1) * 8;
                ldsm_x4(qf[kk], sw_addr(sQ, row, colh));
            }
        }

        const uint32_t kbuf = sK[t & 1], vbuf = sV[t & 1];

        // this warp's 4 slabs (16 keys each)
#pragma unroll
        for (int jj = 0; jj < 4; jj++) {
            const int j = kg * 4 + jj;
            float s0[4] = {0.f, 0.f, 0.f, 0.f};
            float s1[4] = {0.f, 0.f, 0.f, 0.f};
#pragma unroll
            for (int kk = 0; kk < 4; kk++) {
                uint32_t kbv[4];
                int row  = j * 16 + (g >> 1) * 8 + li;
                int colh = kk * 16 + (g & 1) * 8;
                ldsm_x4(kbv, sw_addr(kbuf, row, colh));
                mma16816(s0, qf[kk], &kbv[0]);
                mma16816(s1, qf[kk], &kbv[2]);
            }

            float e00 = ex2f(s0[0]);
            float e01 = ex2f(s0[1]);
            float e02 = ex2f(s0[2]);
            float e03 = ex2f(s0[3]);
            float e10 = ex2f(s1[0]);
            float e11 = ex2f(s1[1]);
            float e12 = ex2f(s1[2]);
            float e13 = ex2f(s1[3]);
            lsum0 += (e00 + e01) + (e10 + e11);
            lsum1 += (e02 + e03) + (e12 + e13);

            uint32_t pa[4];
            __half2 h;
            h = __floats2half2_rn(e00, e01); pa[0] = *reinterpret_cast<uint32_t*>(&h);
            h = __floats2half2_rn(e02, e03); pa[1] = *reinterpret_cast<uint32_t*>(&h);
            h = __floats2half2_rn(e10, e11); pa[2] = *reinterpret_cast<uint32_t*>(&h);
            h = __floats2half2_rn(e12, e13); pa[3] = *reinterpret_cast<uint32_t*>(&h);

#pragma unroll
            for (int p = 0; p < 4; p++) {
                uint32_t vb[4];
                int row  = j * 16 + (g & 1) * 8 + li;
                int colh = p * 16 + (g >> 1) * 8;
                ldsm_x4_t(vb, sw_addr(vbuf, row, colh));
                mma16816(O[2 * p],     pa, &vb[0]);
                mma16816(O[2 * p + 1], pa, &vb[2]);
            }
        }
        __syncthreads();
    }

    // reduce lsum across quad
    lsum0 += __shfl_xor_sync(0xffffffffu, lsum0, 1);
    lsum0 += __shfl_xor_sync(0xffffffffu, lsum0, 2);
    lsum1 += __shfl_xor_sync(0xffffffffu, lsum1, 1);
    lsum1 += __shfl_xor_sync(0xffffffffu, lsum1, 2);

    // merge warp-group partials via smem (reuse K buffers; loop is done)
    float* sO1 = reinterpret_cast<float*>(sm + OFF_K0);         // [64][64]
    float* sL1 = reinterpret_cast<float*>(sm + OFF_K0 + 16384); // [64]

    const int r  = lane >> 2;
    const int cc = (lane & 3) * 2;
    if (kg == 1) {
        int lr0 = qb + r, lr1 = qb + r + 8;
#pragma unroll
        for (int nb = 0; nb < 8; nb++) {
            sO1[lr0 * 64 + nb * 8 + cc]     = O[nb][0];
            sO1[lr0 * 64 + nb * 8 + cc + 1] = O[nb][1];
            sO1[lr1 * 64 + nb * 8 + cc]     = O[nb][2];
            sO1[lr1 * 64 + nb * 8 + cc + 1] = O[nb][3];
        }
        if ((lane & 3) == 0) { sL1[lr0] = lsum0; sL1[lr1] = lsum1; }
    }
    __syncthreads();
    if (kg == 0) {
        int lr0 = qb + r, lr1 = qb + r + 8;
        float inv0 = 1.f / (lsum0 + sL1[lr0]);
        float inv1 = 1.f / (lsum1 + sL1[lr1]);
        float* row0p = &out[(size_t)(b * SEQ + q0 + lr0) * HEAD];
        float* row1p = &out[(size_t)(b * SEQ + q0 + lr1) * HEAD];
#pragma unroll
        for (int nb = 0; nb < 8; nb++) {
            float2 v0 = make_float2((O[nb][0] + sO1[lr0 * 64 + nb * 8 + cc])     * inv0,
                                    (O[nb][1] + sO1[lr0 * 64 + nb * 8 + cc + 1]) * inv0);
            float2 v1 = make_float2((O[nb][2] + sO1[lr1 * 64 + nb * 8 + cc])     * inv1,
                                    (O[nb][3] + sO1[lr1 * 64 + nb * 8 + cc + 1]) * inv1);
            *reinterpret_cast<float2*>(row0p + nb * 8 + cc) = v0;
            *reinterpret_cast<float2*>(row1p + nb * 8 + cc) = v1;
        }
    }
}

// ---------------------------------------------------------------------------
extern "C" void kernel_launch(void* const* d_in, const int* in_sizes, int n_in,
                              void* d_out, int out_size)
{
    const float* x  = (const float*)d_in[0];
    const float* Wq = (const float*)d_in[1];
    const float* bq = (const float*)d_in[2];
    const float* Wk = (const float*)d_in[3];
    const float* bk = (const float*)d_in[4];
    const float* Wv = (const float*)d_in[5];
    const float* bv = (const float*)d_in[6];
    float* out = (float*)d_out;

    wsplit_kernel<<<dim3(24, 3), 256>>>(Wq, Wk, Wv);

    cudaFuncSetAttribute(qkv_hmma_kernel,
                         cudaFuncAttributeMaxDynamicSharedMemorySize, PROJ_SMEM);
    qkv_hmma_kernel<<<NROW / 128, 256, PROJ_SMEM>>>(x, bq, bk, bv);

    cudaFuncSetAttribute(attn_hmma_kernel,
                         cudaFuncAttributeMaxDynamicSharedMemorySize, ATTN_SMEM);
    attn_hmma_kernel<<<dim3(SEQ / BM, BATCH), 256, ATTN_SMEM>>>(out);
}

// round 12
// speedup vs baseline: 1.1141x; 1.0034x over previous
#include <cuda_runtime.h>
#include <cuda_fp16.h>
#include <cstdint>

#define D_MODEL 768
#define HEAD    64
#define BATCH   8
#define SEQ     2048
#define NROW    (BATCH * SEQ)

// Scale folded into Q: scores come out in log2 domain.
#define QSC 0.1803368801111244f   // 0.125 * log2(e)

// Scratch (no device allocation allowed).
__device__ __half g_Q[NROW * HEAD];
__device__ __half g_K[NROW * HEAD];
__device__ __half g_V[NROW * HEAD];
__device__ __half g_Wth[192 * D_MODEL];   // W^T fp16 [n][k] (Wq pre-scaled)

// ---------------------------------------------------------------------------
// common helpers
// ---------------------------------------------------------------------------
__device__ __forceinline__ uint32_t smem_u32(const void* p) {
    uint32_t a;
    asm("{ .reg .u64 t; cvta.to.shared.u64 t, %1; cvt.u32.u64 %0, t; }"
        : "=r"(a) : "l"(p));
    return a;
}
// 128B rows
__device__ __forceinline__ uint32_t sw_addr(uint32_t base, int row, int colh) {
    return base + row * 128 + (((uint32_t)(colh * 2)) ^ (((uint32_t)(row & 7)) << 4));
}
__device__ __forceinline__ void ldsm_x4(uint32_t* r, uint32_t addr) {
    asm volatile("ldmatrix.sync.aligned.m8n8.x4.shared.b16 {%0,%1,%2,%3}, [%4];"
                 : "=r"(r[0]), "=r"(r[1]), "=r"(r[2]), "=r"(r[3]) : "r"(addr));
}
__device__ __forceinline__ void ldsm_x4_t(uint32_t* r, uint32_t addr) {
    asm volatile("ldmatrix.sync.aligned.m8n8.x4.trans.shared.b16 {%0,%1,%2,%3}, [%4];"
                 : "=r"(r[0]), "=r"(r[1]), "=r"(r[2]), "=r"(r[3]) : "r"(addr));
}
__device__ __forceinline__ void mma16816(float* d, const uint32_t* a, const uint32_t* b) {
    asm volatile(
        "mma.sync.aligned.m16n8k16.row.col.f32.f16.f16.f32 "
        "{%0,%1,%2,%3}, {%4,%5,%6,%7}, {%8,%9}, {%0,%1,%2,%3};"
        : "+f"(d[0]), "+f"(d[1]), "+f"(d[2]), "+f"(d[3])
        : "r"(a[0]), "r"(a[1]), "r"(a[2]), "r"(a[3]), "r"(b[0]), "r"(b[1]));
}
__device__ __forceinline__ float ex2f(float x) {
    float y;
    asm("ex2.approx.f32 %0, %1;" : "=f"(y) : "f"(x));
    return y;
}
#define CP16(dst, src) \
    asm volatile("cp.async.cg.shared.global [%0], [%1], 16;" \
                 :: "r"(dst), "l"(src) : "memory")
#define CP_COMMIT() asm volatile("cp.async.commit_group;" ::: "memory")

// ---------------------------------------------------------------------------
// Kernel 0: W transpose + fp16 convert -> g_Wth [n][k] (Wq scaled by QSC).
// grid (24, 3): 32-k x 64-n tiles, 256 threads, vectorized.
// ---------------------------------------------------------------------------
__global__ __launch_bounds__(256) void wsplit_kernel(
    const float* __restrict__ Wq, const float* __restrict__ Wk,
    const float* __restrict__ Wv)
{
    __shared__ float tile[32][65];
    const float* W = (blockIdx.y == 0) ? Wq : (blockIdx.y == 1) ? Wk : Wv;
    const float sc = (blockIdx.y == 0) ? QSC : 1.0f;
    const int kbase = blockIdx.x * 32;
    const int tid = threadIdx.x;
#pragma unroll
    for (int i = 0; i < 2; i++) {
        int f4 = tid + 256 * i;
        int k = f4 >> 4, c4 = f4 & 15;
        float4 v = *reinterpret_cast<const float4*>(&W[(size_t)(kbase + k) * 64 + c4 * 4]);
        tile[k][c4 * 4 + 0] = v.x;
        tile[k][c4 * 4 + 1] = v.y;
        tile[k][c4 * 4 + 2] = v.z;
        tile[k][c4 * 4 + 3] = v.w;
    }
    __syncthreads();
#pragma unroll
    for (int j = 0; j < 4; j++) {
        int idx = tid + 256 * j;
        int n = idx >> 4, kp = idx & 15;
        __half2 h = __floats2half2_rn(tile[2 * kp][n] * sc, tile[2 * kp + 1][n] * sc);
        *reinterpret_cast<__half2*>(
            &g_Wth[(size_t)(blockIdx.y * 64 + n) * D_MODEL + kbase + 2 * kp]) = h;
    }
}

// ---------------------------------------------------------------------------
// Kernel 1: HMMA QKV projection (round-5 proven structure).
// C[16384,192] = Xh · Wh (fp32 accumulate). BM=128, N=192, BK=64.
// ---------------------------------------------------------------------------
#define NCHUNK (D_MODEL / 64)
#define PXH 0
#define PWH0 16384
#define PWH1 40960
#define PROJ_SMEM 65536

__global__ __launch_bounds__(256, 1) void qkv_hmma_kernel(
    const float* __restrict__ x,
    const float* __restrict__ bq, const float* __restrict__ bk,
    const float* __restrict__ bv)
{
    extern __shared__ char sm[];
    const uint32_t sb = smem_u32(sm);
    const int tid  = threadIdx.x;
    const int lane = tid & 31;
    const int warp = tid >> 5;
    const int g    = lane >> 3, li = lane & 7;
    const int mw   = warp >> 1;
    const int nw   = warp & 1;
    const int row0 = blockIdx.x * 128;

    const uint32_t sWH[2] = { sb + PWH0, sb + PWH1 };

    auto issue_w = [&](int c) {
#pragma unroll
        for (int i = 0; i < 6; i++) {
            int idx = tid + 256 * i;
            int n = idx >> 3, c16 = idx & 7;
            uint32_t off = n * 128 + (((uint32_t)(c16 * 16)) ^ (((uint32_t)(n & 7)) << 4));
            CP16(sWH[c & 1] + off, g_Wth + (size_t)n * D_MODEL + c * 64 + c16 * 8);
        }
    };

    float xr[32];
    auto ldg_x = [&](int c) {
#pragma unroll
        for (int i = 0; i < 8; i++) {
            int f = tid + 256 * i;
            int r = f >> 4, c4 = f & 15;
            float4 v = *reinterpret_cast<const float4*>(
                &x[(size_t)(row0 + r) * D_MODEL + c * 64 + c4 * 4]);
            xr[4 * i] = v.x; xr[4 * i + 1] = v.y; xr[4 * i + 2] = v.z; xr[4 * i + 3] = v.w;
        }
    };

    issue_w(0); CP_COMMIT();
    ldg_x(0);

    float acc[2][12][4];
#pragma unroll
    for (int mi = 0; mi < 2; mi++)
#pragma unroll
        for (int nj = 0; nj < 12; nj++)
#pragma unroll
            for (int i = 0; i < 4; i++) acc[mi][nj][i] = 0.f;

    for (int c = 0; c < NCHUNK; c++) {
        __syncthreads();
#pragma unroll
        for (int i = 0; i < 8; i++) {
            int f = tid + 256 * i;
            int r = f >> 4, c4 = f & 15;
            __half2 h0 = __floats2half2_rn(xr[4 * i],     xr[4 * i + 1]);
            __half2 h1 = __floats2half2_rn(xr[4 * i + 2], xr[4 * i + 3]);
            uint32_t off = r * 128 + (((uint32_t)(c4 * 8)) ^ (((uint32_t)(r & 7)) << 4));
            uint2 hv = make_uint2(*reinterpret_cast<uint32_t*>(&h0),
                                  *reinterpret_cast<uint32_t*>(&h1));
            *reinterpret_cast<uint2*>(sm + PXH + off) = hv;
        }
        if (c + 1 < NCHUNK) {
            issue_w(c + 1); CP_COMMIT();
            asm volatile("cp.async.wait_group 1;" ::: "memory");
        } else {
            asm volatile("cp.async.wait_group 0;" ::: "memory");
        }
        __syncthreads();
        if (c + 1 < NCHUNK) ldg_x(c + 1);

        const uint32_t whb = sWH[c & 1];
#pragma unroll
        for (int kk = 0; kk < 4; kk++) {
            uint32_t ah[2][4];
#pragma unroll
            for (int mi = 0; mi < 2; mi++) {
                int row  = mw * 32 + mi * 16 + (g & 1) * 8 + li;
                int colh = kk * 16 + (g >> 1) * 8;
                ldsm_x4(ah[mi], sw_addr(sb + PXH, row, colh));
            }
#pragma unroll
            for (int nj = 0; nj < 6; nj++) {
                uint32_t bh[4];
                int nrow = nw * 96 + nj * 16 + (g >> 1) * 8 + li;
                int colh = kk * 16 + (g & 1) * 8;
                ldsm_x4(bh, sw_addr(whb, nrow, colh));
#pragma unroll
                for (int mi = 0; mi < 2; mi++) {
                    mma16816(acc[mi][2 * nj],     ah[mi], &bh[0]);
                    mma16816(acc[mi][2 * nj + 1], ah[mi], &bh[2]);
                }
            }
        }
    }

    const int r  = lane >> 2;
    const int cc = (lane & 3) * 2;
    float2 biasv[12];
#pragma unroll
    for (int nj = 0; nj < 12; nj++) {
        int ncol = nw * 96 + nj * 8 + cc;
        const float* bp = (ncol < 64) ? bq : (ncol < 128) ? bk : bv;
        float s = (ncol < 64) ? QSC : 1.0f;
        int colw = ncol & 63;
        biasv[nj] = make_float2(bp[colw] * s, bp[colw + 1] * s);
    }
#pragma unroll
    for (int mi = 0; mi < 2; mi++) {
#pragma unroll
        for (int h = 0; h < 2; h++) {
            int grow = row0 + mw * 32 + mi * 16 + r + h * 8;
#pragma unroll
            for (int nj = 0; nj < 12; nj++) {
                int ncol = nw * 96 + nj * 8 + cc;
                __half* dst = (ncol < 64) ? g_Q : (ncol < 128) ? g_K : g_V;
                int colw = ncol & 63;
                __half2 v = __floats2half2_rn(acc[mi][nj][2 * h] + biasv[nj].x,
                                              acc[mi][nj][2 * h + 1] + biasv[nj].y);
                *reinterpret_cast<__half2*>(&dst[(size_t)grow * HEAD + colw]) = v;
            }
        }
    }
}

// ---------------------------------------------------------------------------
// Kernel 2: HMMA flash attention, 8 warps, intra-block slab split.
// BM=64 queries, BN=128 keys/tile. Warp w: qgroup = w&3 (16 q rows),
// kgroup = w>>2 (slabs 0-3 or 4-7 of each tile). Partials merged in smem.
// grid (SEQ/64, BATCH) = 256 blocks; __launch_bounds__(256,2) -> 2 blocks/SM.
// ---------------------------------------------------------------------------
#define BM 64
#define BN 128
#define NT (SEQ / BN)
#define OFF_Q   0
#define OFF_K0  8192
#define OFF_K1  24576
#define OFF_V0  40960
#define OFF_V1  57344
#define ATTN_SMEM 73728

__global__ __launch_bounds__(256, 2) void attn_hmma_kernel(float* __restrict__ out)
{
    extern __shared__ char sm[];
    const uint32_t sb = smem_u32(sm);
    const int tid  = threadIdx.x;
    const int lane = tid & 31;
    const int warp = tid >> 5;
    const int qw   = warp & 3;        // q-group (16 rows)
    const int kg   = warp >> 2;       // slab half (0: j=0..3, 1: j=4..7)
    const int b    = blockIdx.y;
    const int q0   = blockIdx.x * BM;
    const int qb   = qw * 16;

    const uint32_t sQ = sb + OFF_Q;
    const uint32_t sK[2] = { sb + OFF_K0, sb + OFF_K1 };
    const uint32_t sV[2] = { sb + OFF_V0, sb + OFF_V1 };

    // loaders: 256 threads. K/V tile = 1024 16B chunks, Q tile = 512.
    auto issue_rows8 = [&](uint32_t dstbase, const __half* src, int row0g) {
#pragma unroll
        for (int i = 0; i < 4; i++) {
            int c   = tid + 256 * i;
            int row = c >> 3, c16 = c & 7;
            uint32_t dst = dstbase + row * 128 +
                (((uint32_t)(c16 * 16)) ^ (((uint32_t)(row & 7)) << 4));
            CP16(dst, src + (size_t)(row0g + row) * HEAD + c16 * 8);
        }
    };
    auto issue_rows4 = [&](uint32_t dstbase, const __half* src, int row0g) {
#pragma unroll
        for (int i = 0; i < 2; i++) {
            int c   = tid + 256 * i;
            int row = c >> 3, c16 = c & 7;
            uint32_t dst = dstbase + row * 128 +
                (((uint32_t)(c16 * 16)) ^ (((uint32_t)(row & 7)) << 4));
            CP16(dst, src + (size_t)(row0g + row) * HEAD + c16 * 8);
        }
    };

    issue_rows4(sQ, g_Q, b * SEQ + q0);
    issue_rows8(sK[0], g_K, b * SEQ);
    issue_rows8(sV[0], g_V, b * SEQ);
    CP_COMMIT();

    const int g = lane >> 3, li = lane & 7;

    uint32_t qf[4][4];
    float    O[8][4];
#pragma unroll
    for (int n = 0; n < 8; n++)
#pragma unroll
        for (int i = 0; i < 4; i++) O[n][i] = 0.f;
    float lsum0 = 0.f, lsum1 = 0.f;

    for (int t = 0; t < NT; t++) {
        if (t + 1 < NT) {
            issue_rows8(sK[(t + 1) & 1], g_K, b * SEQ + (t + 1) * BN);
            issue_rows8(sV[(t + 1) & 1], g_V, b * SEQ + (t + 1) * BN);
            CP_COMMIT();
            asm volatile("cp.async.wait_group 1;" ::: "memory");
        } else {
            asm volatile("cp.async.wait_group 0;" ::: "memory");
        }
        __syncthreads();

        if (t == 0) {
#pragma unroll
            for (int kk = 0; kk < 4; kk++) {
                int row  = qb + (g & 1) * 8 + li;
                int colh = kk * 16 + (g >> 1) * 8;
                ldsm_x4(qf[kk], sw_addr(sQ, row, colh));
            }
        }

        const uint32_t kbuf = sK[t & 1], vbuf = sV[t & 1];

        // this warp's 4 slabs (16 keys each)
#pragma unroll
        for (int jj = 0; jj < 4; jj++) {
            const int j = kg * 4 + jj;
            float s0[4] = {0.f, 0.f, 0.f, 0.f};
            float s1[4] = {0.f, 0.f, 0.f, 0.f};
#pragma unroll
            for (int kk = 0; kk < 4; kk++) {
                uint32_t kbv[4];
                int row  = j * 16 + (g >> 1) * 8 + li;
                int colh = kk * 16 + (g & 1) * 8;
                ldsm_x4(kbv, sw_addr(kbuf, row, colh));
                mma16816(s0, qf[kk], &kbv[0]);
                mma16816(s1, qf[kk], &kbv[2]);
            }

            float e00 = ex2f(s0[0]);
            float e01 = ex2f(s0[1]);
            float e02 = ex2f(s0[2]);
            float e03 = ex2f(s0[3]);
            float e10 = ex2f(s1[0]);
            float e11 = ex2f(s1[1]);
            float e12 = ex2f(s1[2]);
            float e13 = ex2f(s1[3]);
            lsum0 += (e00 + e01) + (e10 + e11);
            lsum1 += (e02 + e03) + (e12 + e13);

            uint32_t pa[4];
            __half2 h;
            h = __floats2half2_rn(e00, e01); pa[0] = *reinterpret_cast<uint32_t*>(&h);
            h = __floats2half2_rn(e02, e03); pa[1] = *reinterpret_cast<uint32_t*>(&h);
            h = __floats2half2_rn(e10, e11); pa[2] = *reinterpret_cast<uint32_t*>(&h);
            h = __floats2half2_rn(e12, e13); pa[3] = *reinterpret_cast<uint32_t*>(&h);

#pragma unroll
            for (int p = 0; p < 4; p++) {
                uint32_t vb[4];
                int row  = j * 16 + (g & 1) * 8 + li;
                int colh = p * 16 + (g >> 1) * 8;
                ldsm_x4_t(vb, sw_addr(vbuf, row, colh));
                mma16816(O[2 * p],     pa, &vb[0]);
                mma16816(O[2 * p + 1], pa, &vb[2]);
            }
        }
        __syncthreads();
    }

    // reduce lsum across quad
    lsum0 += __shfl_xor_sync(0xffffffffu, lsum0, 1);
    lsum0 += __shfl_xor_sync(0xffffffffu, lsum0, 2);
    lsum1 += __shfl_xor_sync(0xffffffffu, lsum1, 1);
    lsum1 += __shfl_xor_sync(0xffffffffu, lsum1, 2);

    // merge warp-group partials via smem (reuse K buffers; loop is done)
    float* sO1 = reinterpret_cast<float*>(sm + OFF_K0);         // [64][64]
    float* sL1 = reinterpret_cast<float*>(sm + OFF_K0 + 16384); // [64]

    const int r  = lane >> 2;
    const int cc = (lane & 3) * 2;
    if (kg == 1) {
        int lr0 = qb + r, lr1 = qb + r + 8;
#pragma unroll
        for (int nb = 0; nb < 8; nb++) {
            sO1[lr0 * 64 + nb * 8 + cc]     = O[nb][0];
            sO1[lr0 * 64 + nb * 8 + cc + 1] = O[nb][1];
            sO1[lr1 * 64 + nb * 8 + cc]     = O[nb][2];
            sO1[lr1 * 64 + nb * 8 + cc + 1] = O[nb][3];
        }
        if ((lane & 3) == 0) { sL1[lr0] = lsum0; sL1[lr1] = lsum1; }
    }
    __syncthreads();
    if (kg == 0) {
        int lr0 = qb + r, lr1 = qb + r + 8;
        float inv0 = 1.f / (lsum0 + sL1[lr0]);
        float inv1 = 1.f / (lsum1 + sL1[lr1]);
        float* row0p = &out[(size_t)(b * SEQ + q0 + lr0) * HEAD];
        float* row1p = &out[(size_t)(b * SEQ + q0 + lr1) * HEAD];
#pragma unroll
        for (int nb = 0; nb < 8; nb++) {
            float2 v0 = make_float2((O[nb][0] + sO1[lr0 * 64 + nb * 8 + cc])     * inv0,
                                    (O[nb][1] + sO1[lr0 * 64 + nb * 8 + cc + 1]) * inv0);
            float2 v1 = make_float2((O[nb][2] + sO1[lr1 * 64 + nb * 8 + cc])     * inv1,
                                    (O[nb][3] + sO1[lr1 * 64 + nb * 8 + cc + 1]) * inv1);
            *reinterpret_cast<float2*>(row0p + nb * 8 + cc) = v0;
            *reinterpret_cast<float2*>(row1p + nb * 8 + cc) = v1;
        }
    }
}

// ---------------------------------------------------------------------------
extern "C" void kernel_launch(void* const* d_in, const int* in_sizes, int n_in,
                              void* d_out, int out_size)
{
    const float* x  = (const float*)d_in[0];
    const float* Wq = (const float*)d_in[1];
    const float* bq = (const float*)d_in[2];
    const float* Wk = (const float*)d_in[3];
    const float* bk = (const float*)d_in[4];
    const float* Wv = (const float*)d_in[5];
    const float* bv = (const float*)d_in[6];
    float* out = (float*)d_out;

    wsplit_kernel<<<dim3(24, 3), 256>>>(Wq, Wk, Wv);

    cudaFuncSetAttribute(qkv_hmma_kernel,
                         cudaFuncAttributeMaxDynamicSharedMemorySize, PROJ_SMEM);
    qkv_hmma_kernel<<<NROW / 128, 256, PROJ_SMEM>>>(x, bq, bk, bv);

    cudaFuncSetAttribute(attn_hmma_kernel,
                         cudaFuncAttributeMaxDynamicSharedMemorySize, ATTN_SMEM);
    attn_hmma_kernel<<<dim3(SEQ / BM, BATCH), 256, ATTN_SMEM>>>(out);
}

// round 13
// speedup vs baseline: 1.1147x; 1.0006x over previous
#include <cuda_runtime.h>
#include <cuda_fp16.h>
#include <cstdint>

#define D_MODEL 768
#define HEAD    64
#define BATCH   8
#define SEQ     2048
#define NROW    (BATCH * SEQ)

// Scale folded into Q: scores come out in log2 domain.
#define QSC 0.1803368801111244f   // 0.125 * log2(e)

// Scratch (no device allocation allowed).
__device__ __half g_Q[NROW * HEAD];
__device__ __half g_K[NROW * HEAD];
__device__ __half g_V[NROW * HEAD];
__device__ __half g_Wth[192 * D_MODEL];   // W^T fp16 [n][k] (Wq pre-scaled)

// ---------------------------------------------------------------------------
// common helpers
// ---------------------------------------------------------------------------
__device__ __forceinline__ uint32_t smem_u32(const void* p) {
    uint32_t a;
    asm("{ .reg .u64 t; cvta.to.shared.u64 t, %1; cvt.u32.u64 %0, t; }"
        : "=r"(a) : "l"(p));
    return a;
}
// 128B rows
__device__ __forceinline__ uint32_t sw_addr(uint32_t base, int row, int colh) {
    return base + row * 128 + (((uint32_t)(colh * 2)) ^ (((uint32_t)(row & 7)) << 4));
}
__device__ __forceinline__ void ldsm_x4(uint32_t* r, uint32_t addr) {
    asm volatile("ldmatrix.sync.aligned.m8n8.x4.shared.b16 {%0,%1,%2,%3}, [%4];"
                 : "=r"(r[0]), "=r"(r[1]), "=r"(r[2]), "=r"(r[3]) : "r"(addr));
}
__device__ __forceinline__ void ldsm_x4_t(uint32_t* r, uint32_t addr) {
    asm volatile("ldmatrix.sync.aligned.m8n8.x4.trans.shared.b16 {%0,%1,%2,%3}, [%4];"
                 : "=r"(r[0]), "=r"(r[1]), "=r"(r[2]), "=r"(r[3]) : "r"(addr));
}
__device__ __forceinline__ void mma16816(float* d, const uint32_t* a, const uint32_t* b) {
    asm volatile(
        "mma.sync.aligned.m16n8k16.row.col.f32.f16.f16.f32 "
        "{%0,%1,%2,%3}, {%4,%5,%6,%7}, {%8,%9}, {%0,%1,%2,%3};"
        : "+f"(d[0]), "+f"(d[1]), "+f"(d[2]), "+f"(d[3])
        : "r"(a[0]), "r"(a[1]), "r"(a[2]), "r"(a[3]), "r"(b[0]), "r"(b[1]));
}
__device__ __forceinline__ float ex2f(float x) {
    float y;
    asm("ex2.approx.f32 %0, %1;" : "=f"(y) : "f"(x));
    return y;
}
#define CP16(dst, src) \
    asm volatile("cp.async.cg.shared.global [%0], [%1], 16;" \
                 :: "r"(dst), "l"(src) : "memory")
#define CP_COMMIT() asm volatile("cp.async.commit_group;" ::: "memory")

// ---------------------------------------------------------------------------
// Kernel 0: W transpose + fp16 convert -> g_Wth [n][k] (Wq scaled by QSC).
// grid (24, 3): 32-k x 64-n tiles, 256 threads, vectorized.
// ---------------------------------------------------------------------------
__global__ __launch_bounds__(256) void wsplit_kernel(
    const float* __restrict__ Wq, const float* __restrict__ Wk,
    const float* __restrict__ Wv)
{
    __shared__ float tile[32][65];
    const float* W = (blockIdx.y == 0) ? Wq : (blockIdx.y == 1) ? Wk : Wv;
    const float sc = (blockIdx.y == 0) ? QSC : 1.0f;
    const int kbase = blockIdx.x * 32;
    const int tid = threadIdx.x;
#pragma unroll
    for (int i = 0; i < 2; i++) {
        int f4 = tid + 256 * i;
        int k = f4 >> 4, c4 = f4 & 15;
        float4 v = *reinterpret_cast<const float4*>(&W[(size_t)(kbase + k) * 64 + c4 * 4]);
        tile[k][c4 * 4 + 0] = v.x;
        tile[k][c4 * 4 + 1] = v.y;
        tile[k][c4 * 4 + 2] = v.z;
        tile[k][c4 * 4 + 3] = v.w;
    }
    __syncthreads();
#pragma unroll
    for (int j = 0; j < 4; j++) {
        int idx = tid + 256 * j;
        int n = idx >> 4, kp = idx & 15;
        __half2 h = __floats2half2_rn(tile[2 * kp][n] * sc, tile[2 * kp + 1][n] * sc);
        *reinterpret_cast<__half2*>(
            &g_Wth[(size_t)(blockIdx.y * 64 + n) * D_MODEL + kbase + 2 * kp]) = h;
    }
}

// ---------------------------------------------------------------------------
// Kernel 1: HMMA QKV projection (round-5 proven structure).
// C[16384,192] = Xh · Wh (fp32 accumulate). BM=128, N=192, BK=64.
// ---------------------------------------------------------------------------
#define NCHUNK (D_MODEL / 64)
#define PXH 0
#define PWH0 16384
#define PWH1 40960
#define PROJ_SMEM 65536

__global__ __launch_bounds__(256, 1) void qkv_hmma_kernel(
    const float* __restrict__ x,
    const float* __restrict__ bq, const float* __restrict__ bk,
    const float* __restrict__ bv)
{
    extern __shared__ char sm[];
    const uint32_t sb = smem_u32(sm);
    const int tid  = threadIdx.x;
    const int lane = tid & 31;
    const int warp = tid >> 5;
    const int g    = lane >> 3, li = lane & 7;
    const int mw   = warp >> 1;
    const int nw   = warp & 1;
    const int row0 = blockIdx.x * 128;

    const uint32_t sWH[2] = { sb + PWH0, sb + PWH1 };

    auto issue_w = [&](int c) {
#pragma unroll
        for (int i = 0; i < 6; i++) {
            int idx = tid + 256 * i;
            int n = idx >> 3, c16 = idx & 7;
            uint32_t off = n * 128 + (((uint32_t)(c16 * 16)) ^ (((uint32_t)(n & 7)) << 4));
            CP16(sWH[c & 1] + off, g_Wth + (size_t)n * D_MODEL + c * 64 + c16 * 8);
        }
    };

    float xr[32];
    auto ldg_x = [&](int c) {
#pragma unroll
        for (int i = 0; i < 8; i++) {
            int f = tid + 256 * i;
            int r = f >> 4, c4 = f & 15;
            float4 v = *reinterpret_cast<const float4*>(
                &x[(size_t)(row0 + r) * D_MODEL + c * 64 + c4 * 4]);
            xr[4 * i] = v.x; xr[4 * i + 1] = v.y; xr[4 * i + 2] = v.z; xr[4 * i + 3] = v.w;
        }
    };

    issue_w(0); CP_COMMIT();
    ldg_x(0);

    float acc[2][12][4];
#pragma unroll
    for (int mi = 0; mi < 2; mi++)
#pragma unroll
        for (int nj = 0; nj < 12; nj++)
#pragma unroll
            for (int i = 0; i < 4; i++) acc[mi][nj][i] = 0.f;

    for (int c = 0; c < NCHUNK; c++) {
        __syncthreads();
#pragma unroll
        for (int i = 0; i < 8; i++) {
            int f = tid + 256 * i;
            int r = f >> 4, c4 = f & 15;
            __half2 h0 = __floats2half2_rn(xr[4 * i],     xr[4 * i + 1]);
            __half2 h1 = __floats2half2_rn(xr[4 * i + 2], xr[4 * i + 3]);
            uint32_t off = r * 128 + (((uint32_t)(c4 * 8)) ^ (((uint32_t)(r & 7)) << 4));
            uint2 hv = make_uint2(*reinterpret_cast<uint32_t*>(&h0),
                                  *reinterpret_cast<uint32_t*>(&h1));
            *reinterpret_cast<uint2*>(sm + PXH + off) = hv;
        }
        if (c + 1 < NCHUNK) {
            issue_w(c + 1); CP_COMMIT();
            asm volatile("cp.async.wait_group 1;" ::: "memory");
        } else {
            asm volatile("cp.async.wait_group 0;" ::: "memory");
        }
        __syncthreads();
        if (c + 1 < NCHUNK) ldg_x(c + 1);

        const uint32_t whb = sWH[c & 1];
#pragma unroll
        for (int kk = 0; kk < 4; kk++) {
            uint32_t ah[2][4];
#pragma unroll
            for (int mi = 0; mi < 2; mi++) {
                int row  = mw * 32 + mi * 16 + (g & 1) * 8 + li;
                int colh = kk * 16 + (g >> 1) * 8;
                ldsm_x4(ah[mi], sw_addr(sb + PXH, row, colh));
            }
#pragma unroll
            for (int nj = 0; nj < 6; nj++) {
                uint32_t bh[4];
                int nrow = nw * 96 + nj * 16 + (g >> 1) * 8 + li;
                int colh = kk * 16 + (g & 1) * 8;
                ldsm_x4(bh, sw_addr(whb, nrow, colh));
#pragma unroll
                for (int mi = 0; mi < 2; mi++) {
                    mma16816(acc[mi][2 * nj],     ah[mi], &bh[0]);
                    mma16816(acc[mi][2 * nj + 1], ah[mi], &bh[2]);
                }
            }
        }
    }

    const int r  = lane >> 2;
    const int cc = (lane & 3) * 2;
    float2 biasv[12];
#pragma unroll
    for (int nj = 0; nj < 12; nj++) {
        int ncol = nw * 96 + nj * 8 + cc;
        const float* bp = (ncol < 64) ? bq : (ncol < 128) ? bk : bv;
        float s = (ncol < 64) ? QSC : 1.0f;
        int colw = ncol & 63;
        biasv[nj] = make_float2(bp[colw] * s, bp[colw + 1] * s);
    }
#pragma unroll
    for (int mi = 0; mi < 2; mi++) {
#pragma unroll
        for (int h = 0; h < 2; h++) {
            int grow = row0 + mw * 32 + mi * 16 + r + h * 8;
#pragma unroll
            for (int nj = 0; nj < 12; nj++) {
                int ncol = nw * 96 + nj * 8 + cc;
                __half* dst = (ncol < 64) ? g_Q : (ncol < 128) ? g_K : g_V;
                int colw = ncol & 63;
                __half2 v = __floats2half2_rn(acc[mi][nj][2 * h] + biasv[nj].x,
                                              acc[mi][nj][2 * h + 1] + biasv[nj].y);
                *reinterpret_cast<__half2*>(&dst[(size_t)grow * HEAD + colw]) = v;
            }
        }
    }
}

// ---------------------------------------------------------------------------
// Kernel 2: HMMA flash attention, 8 warps, intra-block slab split.
// BM=64 queries, BN=128 keys/tile. Warp w: qgroup = w&3 (16 q rows),
// kgroup = w>>2 (slabs 0-3 or 4-7 of each tile). Partials merged in smem.
// grid (SEQ/64, BATCH) = 256 blocks; __launch_bounds__(256,2) -> 2 blocks/SM.
// ---------------------------------------------------------------------------
#define BM 64
#define BN 128
#define NT (SEQ / BN)
#define OFF_Q   0
#define OFF_K0  8192
#define OFF_K1  24576
#define OFF_V0  40960
#define OFF_V1  57344
#define ATTN_SMEM 73728

__global__ __launch_bounds__(256, 2) void attn_hmma_kernel(float* __restrict__ out)
{
    extern __shared__ char sm[];
    const uint32_t sb = smem_u32(sm);
    const int tid  = threadIdx.x;
    const int lane = tid & 31;
    const int warp = tid >> 5;
    const int qw   = warp & 3;        // q-group (16 rows)
    const int kg   = warp >> 2;       // slab half (0: j=0..3, 1: j=4..7)
    const int b    = blockIdx.y;
    const int q0   = blockIdx.x * BM;
    const int qb   = qw * 16;

    const uint32_t sQ = sb + OFF_Q;
    const uint32_t sK[2] = { sb + OFF_K0, sb + OFF_K1 };
    const uint32_t sV[2] = { sb + OFF_V0, sb + OFF_V1 };

    // loaders: 256 threads. K/V tile = 1024 16B chunks, Q tile = 512.
    auto issue_rows8 = [&](uint32_t dstbase, const __half* src, int row0g) {
#pragma unroll
        for (int i = 0; i < 4; i++) {
            int c   = tid + 256 * i;
            int row = c >> 3, c16 = c & 7;
            uint32_t dst = dstbase + row * 128 +
                (((uint32_t)(c16 * 16)) ^ (((uint32_t)(row & 7)) << 4));
            CP16(dst, src + (size_t)(row0g + row) * HEAD + c16 * 8);
        }
    };
    auto issue_rows4 = [&](uint32_t dstbase, const __half* src, int row0g) {
#pragma unroll
        for (int i = 0; i < 2; i++) {
            int c   = tid + 256 * i;
            int row = c >> 3, c16 = c & 7;
            uint32_t dst = dstbase + row * 128 +
                (((uint32_t)(c16 * 16)) ^ (((uint32_t)(row & 7)) << 4));
            CP16(dst, src + (size_t)(row0g + row) * HEAD + c16 * 8);
        }
    };

    issue_rows4(sQ, g_Q, b * SEQ + q0);
    issue_rows8(sK[0], g_K, b * SEQ);
    issue_rows8(sV[0], g_V, b * SEQ);
    CP_COMMIT();

    const int g = lane >> 3, li = lane & 7;

    uint32_t qf[4][4];
    float    O[8][4];
#pragma unroll
    for (int n = 0; n < 8; n++)
#pragma unroll
        for (int i = 0; i < 4; i++) O[n][i] = 0.f;
    float lsum0 = 0.f, lsum1 = 0.f;

    for (int t = 0; t < NT; t++) {
        if (t + 1 < NT) {
            issue_rows8(sK[(t + 1) & 1], g_K, b * SEQ + (t + 1) * BN);
            issue_rows8(sV[(t + 1) & 1], g_V, b * SEQ + (t + 1) * BN);
            CP_COMMIT();
            asm volatile("cp.async.wait_group 1;" ::: "memory");
        } else {
            asm volatile("cp.async.wait_group 0;" ::: "memory");
        }
        __syncthreads();

        if (t == 0) {
#pragma unroll
            for (int kk = 0; kk < 4; kk++) {
                int row  = qb + (g & 1) * 8 + li;
                int colh = kk * 16 + (g >> 1) * 8;
                ldsm_x4(qf[kk], sw_addr(sQ, row, colh));
            }
        }

        const uint32_t kbuf = sK[t & 1], vbuf = sV[t & 1];

        // this warp's 4 slabs (16 keys each)
#pragma unroll
        for (int jj = 0; jj < 4; jj++) {
            const int j = kg * 4 + jj;
            float s0[4] = {0.f, 0.f, 0.f, 0.f};
            float s1[4] = {0.f, 0.f, 0.f, 0.f};
#pragma unroll
            for (int kk = 0; kk < 4; kk++) {
                uint32_t kbv[4];
                int row  = j * 16 + (g >> 1) * 8 + li;
                int colh = kk * 16 + (g & 1) * 8;
                ldsm_x4(kbv, sw_addr(kbuf, row, colh));
                mma16816(s0, qf[kk], &kbv[0]);
                mma16816(s1, qf[kk], &kbv[2]);
            }

            float e00 = ex2f(s0[0]);
            float e01 = ex2f(s0[1]);
            float e02 = ex2f(s0[2]);
            float e03 = ex2f(s0[3]);
            float e10 = ex2f(s1[0]);
            float e11 = ex2f(s1[1]);
            float e12 = ex2f(s1[2]);
            float e13 = ex2f(s1[3]);
            lsum0 += (e00 + e01) + (e10 + e11);
            lsum1 += (e02 + e03) + (e12 + e13);

            uint32_t pa[4];
            __half2 h;
            h = __floats2half2_rn(e00, e01); pa[0] = *reinterpret_cast<uint32_t*>(&h);
            h = __floats2half2_rn(e02, e03); pa[1] = *reinterpret_cast<uint32_t*>(&h);
            h = __floats2half2_rn(e10, e11); pa[2] = *reinterpret_cast<uint32_t*>(&h);
            h = __floats2half2_rn(e12, e13); pa[3] = *reinterpret_cast<uint32_t*>(&h);

#pragma unroll
            for (int p = 0; p < 4; p++) {
                uint32_t vb[4];
                int row  = j * 16 + (g & 1) * 8 + li;
                int colh = p * 16 + (g >> 1) * 8;
                ldsm_x4_t(vb, sw_addr(vbuf, row, colh));
                mma16816(O[2 * p],     pa, &vb[0]);
                mma16816(O[2 * p + 1], pa, &vb[2]);
            }
        }
        __syncthreads();
    }

    // reduce lsum across quad
    lsum0 += __shfl_xor_sync(0xffffffffu, lsum0, 1);
    lsum0 += __shfl_xor_sync(0xffffffffu, lsum0, 2);
    lsum1 += __shfl_xor_sync(0xffffffffu, lsum1, 1);
    lsum1 += __shfl_xor_sync(0xffffffffu, lsum1, 2);

    // merge warp-group partials via smem (reuse K buffers; loop is done)
    float* sO1 = reinterpret_cast<float*>(sm + OFF_K0);         // [64][64]
    float* sL1 = reinterpret_cast<float*>(sm + OFF_K0 + 16384); // [64]

    const int r  = lane >> 2;
    const int cc = (lane & 3) * 2;
    if (kg == 1) {
        int lr0 = qb + r, lr1 = qb + r + 8;
#pragma unroll
        for (int nb = 0; nb < 8; nb++) {
            sO1[lr0 * 64 + nb * 8 + cc]     = O[nb][0];
            sO1[lr0 * 64 + nb * 8 + cc + 1] = O[nb][1];
            sO1[lr1 * 64 + nb * 8 + cc]     = O[nb][2];
            sO1[lr1 * 64 + nb * 8 + cc + 1] = O[nb][3];
        }
        if ((lane & 3) == 0) { sL1[lr0] = lsum0; sL1[lr1] = lsum1; }
    }
    __syncthreads();
    if (kg == 0) {
        int lr0 = qb + r, lr1 = qb + r + 8;
        float inv0 = 1.f / (lsum0 + sL1[lr0]);
        float inv1 = 1.f / (lsum1 + sL1[lr1]);
        float* row0p = &out[(size_t)(b * SEQ + q0 + lr0) * HEAD];
        float* row1p = &out[(size_t)(b * SEQ + q0 + lr1) * HEAD];
#pragma unroll
        for (int nb = 0; nb < 8; nb++) {
            float2 v0 = make_float2((O[nb][0] + sO1[lr0 * 64 + nb * 8 + cc])     * inv0,
                                    (O[nb][1] + sO1[lr0 * 64 + nb * 8 + cc + 1]) * inv0);
            float2 v1 = make_float2((O[nb][2] + sO1[lr1 * 64 + nb * 8 + cc])     * inv1,
                                    (O[nb][3] + sO1[lr1 * 64 + nb * 8 + cc + 1]) * inv1);
            *reinterpret_cast<float2*>(row0p + nb * 8 + cc) = v0;
            *reinterpret_cast<float2*>(row1p + nb * 8 + cc) = v1;
        }
    }
}

// ---------------------------------------------------------------------------
extern "C" void kernel_launch(void* const* d_in, const int* in_sizes, int n_in,
                              void* d_out, int out_size)
{
    const float* x  = (const float*)d_in[0];
    const float* Wq = (const float*)d_in[1];
    const float* bq = (const float*)d_in[2];
    const float* Wk = (const float*)d_in[3];
    const float* bk = (const float*)d_in[4];
    const float* Wv = (const float*)d_in[5];
    const float* bv = (const float*)d_in[6];
    float* out = (float*)d_out;

    wsplit_kernel<<<dim3(24, 3), 256>>>(Wq, Wk, Wv);

    cudaFuncSetAttribute(qkv_hmma_kernel,
                         cudaFuncAttributeMaxDynamicSharedMemorySize, PROJ_SMEM);
    qkv_hmma_kernel<<<NROW / 128, 256, PROJ_SMEM>>>(x, bq, bk, bv);

    cudaFuncSetAttribute(attn_hmma_kernel,
                         cudaFuncAttributeMaxDynamicSharedMemorySize, ATTN_SMEM);
    attn_hmma_kernel<<<dim3(SEQ / BM, BATCH), 256, ATTN_SMEM>>>(out);
}